// round 13
// baseline (speedup 1.0000x reference)
#include <cuda_runtime.h>
#include <cuda_bf16.h>
#include <cstdint>

constexpr int NN  = 100000;   // nodes
constexpr int EE  = 1600000;  // edges
constexpr int GG  = 256;      // graphs
constexpr int DIN = 64;
constexpr int HID = 128;

// Scratch (device globals — no allocation allowed)
__device__ uint32_t g_aggHi[(size_t)NN * 64];   // packed bf16x2 hi plane (K<=128)
__device__ uint32_t g_aggLo[(size_t)NN * 64];   // packed bf16x2 lo plane
__device__ float g_h1 [(size_t)NN * HID];
__device__ float g_gsum[GG];
// CSR scratch
__device__ int g_cnt [NN];
__device__ int g_off [NN];
__device__ int g_pos [EE];
__device__ int g_ssrc[EE];

// ===========================================================================
// Warp-level tensor-core primitives (base ISA: valid on target sm_100)
// ===========================================================================
__device__ __forceinline__ uint32_t smem_u32(const void* p) {
    uint32_t a;
    asm("{ .reg .u64 t; cvta.to.shared.u64 t, %1; cvt.u32.u64 %0, t; }" : "=r"(a) : "l"(p));
    return a;
}

__device__ __forceinline__ void ldmatrix_x4(uint32_t* r, uint32_t addr) {
    asm volatile("ldmatrix.sync.aligned.m8n8.x4.shared.b16 {%0,%1,%2,%3}, [%4];"
                 : "=r"(r[0]), "=r"(r[1]), "=r"(r[2]), "=r"(r[3]) : "r"(addr));
}
__device__ __forceinline__ void ldmatrix_x2(uint32_t* r, uint32_t addr) {
    asm volatile("ldmatrix.sync.aligned.m8n8.x2.shared.b16 {%0,%1}, [%2];"
                 : "=r"(r[0]), "=r"(r[1]) : "r"(addr));
}

// D(16x8,f32) += A(16x16,bf16,row) * B(16x8,bf16,col)
__device__ __forceinline__ void mma_16816(float* d, const uint32_t* a, const uint32_t* b) {
    asm volatile(
        "mma.sync.aligned.m16n8k16.row.col.f32.bf16.bf16.f32 "
        "{%0,%1,%2,%3}, {%4,%5,%6,%7}, {%8,%9}, {%0,%1,%2,%3};"
        : "+f"(d[0]), "+f"(d[1]), "+f"(d[2]), "+f"(d[3])
        : "r"(a[0]), "r"(a[1]), "r"(a[2]), "r"(a[3]), "r"(b[0]), "r"(b[1]));
}

// Split two floats into packed bf16x2 hi and lo words
__device__ __forceinline__ void split2(float x, float y, uint32_t& hp, uint32_t& lp) {
    __nv_bfloat16 hx = __float2bfloat16(x), hy = __float2bfloat16(y);
    __nv_bfloat16 lx = __float2bfloat16(x - __bfloat162float(hx));
    __nv_bfloat16 ly = __float2bfloat16(y - __bfloat162float(hy));
    hp = ((uint32_t)__bfloat16_as_ushort(hy) << 16) | __bfloat16_as_ushort(hx);
    lp = ((uint32_t)__bfloat16_as_ushort(ly) << 16) | __bfloat16_as_ushort(lx);
}

// ===========================================================================
// CSR build: zero -> histogram(+slot) -> scan -> reorder
// hist/reorder process 4 edges per thread (int4 loads, MLP=4).
// ===========================================================================
__global__ void zero_cnt() {
    int t = blockIdx.x * blockDim.x + threadIdx.x;
    if (t < NN) g_cnt[t] = 0;
    if (t < GG) g_gsum[t] = 0.f;
}

__global__ void hist_kernel(const int* __restrict__ dst) {
    int t = blockIdx.x * blockDim.x + threadIdx.x;
    int e = t * 4;
    if (e >= EE) return;
    int4 d4 = __ldg((const int4*)dst + t);
    int p0 = atomicAdd(&g_cnt[d4.x], 1);
    int p1 = atomicAdd(&g_cnt[d4.y], 1);
    int p2 = atomicAdd(&g_cnt[d4.z], 1);
    int p3 = atomicAdd(&g_cnt[d4.w], 1);
    g_pos[e]     = p0;
    g_pos[e + 1] = p1;
    g_pos[e + 2] = p2;
    g_pos[e + 3] = p3;
}

constexpr int SCAN_T  = 1024;
constexpr int SCAN_CH = (NN + SCAN_T - 1) / SCAN_T;   // 98

__global__ void scan_kernel() {
    __shared__ int ssum[SCAN_T];
    int t = threadIdx.x;
    int base = t * SCAN_CH;
    int s = 0;
    #pragma unroll 4
    for (int i = 0; i < SCAN_CH; i++) {
        int j = base + i;
        if (j < NN) s += g_cnt[j];
    }
    ssum[t] = s;
    __syncthreads();
    for (int d = 1; d < SCAN_T; d <<= 1) {
        int v = (t >= d) ? ssum[t - d] : 0;
        __syncthreads();
        ssum[t] += v;
        __syncthreads();
    }
    int run = (t > 0) ? ssum[t - 1] : 0;
    for (int i = 0; i < SCAN_CH; i++) {
        int j = base + i;
        if (j < NN) { g_off[j] = run; run += g_cnt[j]; }
    }
}

__global__ void reorder_kernel(const int* __restrict__ src,
                               const int* __restrict__ dst) {
    int t = blockIdx.x * blockDim.x + threadIdx.x;
    int e = t * 4;
    if (e >= EE) return;
    int4 s4 = __ldg((const int4*)src + t);
    int4 d4 = __ldg((const int4*)dst + t);
    int4 p4 = __ldg((const int4*)g_pos + t);
    int o0 = __ldg(&g_off[d4.x]);
    int o1 = __ldg(&g_off[d4.y]);
    int o2 = __ldg(&g_off[d4.z]);
    int o3 = __ldg(&g_off[d4.w]);
    g_ssrc[o0 + p4.x] = s4.x;
    g_ssrc[o1 + p4.y] = s4.y;
    g_ssrc[o2 + p4.z] = s4.z;
    g_ssrc[o3 + p4.w] = s4.w;
}

// ===========================================================================
// Gather aggregation -> bf16 hi/lo planes: agg[n] = x[n] + sum_{nbr} x[s]
// gather64: 2 nodes per warp (16 lanes x float4), 8 rows in flight per node.
// gather128: 1 node per warp (32 lanes x float4), 8 rows in flight.
// ===========================================================================
__global__ void gather_split_64(const float* __restrict__ x) {
    int gw   = (blockIdx.x * blockDim.x + threadIdx.x) >> 5;
    int half = (threadIdx.x >> 4) & 1;
    int hl   = threadIdx.x & 15;
    int nw   = (gridDim.x * blockDim.x) >> 5;
    for (int p = gw; p * 2 < NN; p += nw) {
        int n = p * 2 + half;               // NN even -> always < NN
        int lo = g_off[n], deg = g_cnt[n];
        float4 acc = __ldg((const float4*)(x + (size_t)n * 64) + hl);
        int i = 0;
        for (; i + 7 < deg; i += 8) {
            int s[8];
            #pragma unroll
            for (int q = 0; q < 8; q++) s[q] = __ldg(&g_ssrc[lo + i + q]);
            float4 v[8];
            #pragma unroll
            for (int q = 0; q < 8; q++)
                v[q] = __ldg((const float4*)(x + (size_t)s[q] * 64) + hl);
            #pragma unroll
            for (int q = 0; q < 8; q++) {
                acc.x += v[q].x; acc.y += v[q].y; acc.z += v[q].z; acc.w += v[q].w;
            }
        }
        for (; i < deg; i++) {
            int s = __ldg(&g_ssrc[lo + i]);
            float4 v = __ldg((const float4*)(x + (size_t)s * 64) + hl);
            acc.x += v.x; acc.y += v.y; acc.z += v.z; acc.w += v.w;
        }
        uint2 hp, lp;
        split2(acc.x, acc.y, hp.x, lp.x);
        split2(acc.z, acc.w, hp.y, lp.y);
        *(uint2*)(g_aggHi + (size_t)n * 32 + hl * 2) = hp;
        *(uint2*)(g_aggLo + (size_t)n * 32 + hl * 2) = lp;
    }
}

__global__ void gather_split_128(const float* __restrict__ x) {
    int gw   = (blockIdx.x * blockDim.x + threadIdx.x) >> 5;
    int lane = threadIdx.x & 31;
    int nw   = (gridDim.x * blockDim.x) >> 5;
    for (int n = gw; n < NN; n += nw) {
        int lo = g_off[n], deg = g_cnt[n];
        float4 acc = __ldg((const float4*)(x + (size_t)n * 128) + lane);
        int i = 0;
        for (; i + 7 < deg; i += 8) {
            int s[8];
            #pragma unroll
            for (int q = 0; q < 8; q++) s[q] = __ldg(&g_ssrc[lo + i + q]);
            float4 v[8];
            #pragma unroll
            for (int q = 0; q < 8; q++)
                v[q] = __ldg((const float4*)(x + (size_t)s[q] * 128) + lane);
            #pragma unroll
            for (int q = 0; q < 8; q++) {
                acc.x += v[q].x; acc.y += v[q].y; acc.z += v[q].z; acc.w += v[q].w;
            }
        }
        for (; i < deg; i++) {
            int s = __ldg(&g_ssrc[lo + i]);
            float4 v = __ldg((const float4*)(x + (size_t)s * 128) + lane);
            acc.x += v.x; acc.y += v.y; acc.z += v.z; acc.w += v.w;
        }
        uint2 hp, lp;
        split2(acc.x, acc.y, hp.x, lp.x);
        split2(acc.z, acc.w, hp.y, lp.y);
        *(uint2*)(g_aggHi + (size_t)n * 64 + lane * 2) = hp;
        *(uint2*)(g_aggLo + (size_t)n * 64 + lane * 2) = lp;
    }
}

// ===========================================================================
// Fused GEMM pair (R10 256-thread layout): out = relu(relu(A@W1+b1)@W2+b2)
// POOL=true (layer 2): fold mean-pool + FC into the epilogue.
// ===========================================================================
template <int K, bool POOL>
__global__ __launch_bounds__(256, 1)
void fused_pair(const uint32_t* __restrict__ aggHi, const uint32_t* __restrict__ aggLo,
                const float* __restrict__ W1, const float* __restrict__ b1,
                const float* __restrict__ W2, const float* __restrict__ b2,
                float* __restrict__ out,
                const int* __restrict__ batch, const float* __restrict__ Wfc,
                int ntiles)
{
    constexpr int KCH1 = K / 16;         // k-chunks of GEMM1
    constexpr int RSB1 = K * 2 + 16;     // sA row stride bytes (conflict-free)
    constexpr int RSB2 = 128 * 2 + 16;   // sI row stride bytes
    constexpr int KW4  = K / 4;          // uint2 copies per row
    extern __shared__ __align__(16) char smem[];
    char* sAhi = smem;
    char* sAlo = smem + 128 * RSB1;
    char* sIhi = smem + 2 * 128 * RSB1;
    char* sIlo = sIhi + 128 * RSB2;
    __shared__ float sRow[128];

    const int tid  = threadIdx.x;
    const int wid  = tid >> 5;
    const int lane = tid & 31;
    const uint32_t uAhi = smem_u32(sAhi), uAlo = smem_u32(sAlo);
    const uint32_t uIhi = smem_u32(sIhi), uIlo = smem_u32(sIlo);

    // ---- Stage W1^T hi/lo into sI (temp), extract B1 fragments ----
    uint32_t B1hi[KCH1][2][2], B1lo[KCH1][2][2];
    for (int i = tid; i < K * 128; i += 256) {
        int k = i >> 7, n = i & 127;                  // W1[k][n], coalesced
        float w = __ldg(&W1[i]);
        __nv_bfloat16 hi = __float2bfloat16(w);
        __nv_bfloat16 lo = __float2bfloat16(w - __bfloat162float(hi));
        *(__nv_bfloat16*)(sIhi + n * RSB1 + k * 2) = hi;
        *(__nv_bfloat16*)(sIlo + n * RSB1 + k * 2) = lo;
    }
    __syncthreads();
    {
        int r = lane & 7, mat = (lane >> 3) & 1;
        #pragma unroll
        for (int j = 0; j < 2; j++) {
            int n = wid * 16 + j * 8 + r;
            #pragma unroll
            for (int c = 0; c < KCH1; c++) {
                uint32_t off = (uint32_t)n * RSB1 + c * 32 + mat * 16;
                ldmatrix_x2(B1hi[c][j], uIhi + off);
                ldmatrix_x2(B1lo[c][j], uIlo + off);
            }
        }
    }
    __syncthreads();

    // ---- Stage W2^T hi/lo into sI (temp), extract B2 fragments ----
    uint32_t B2hi[8][2][2], B2lo[8][2][2];
    for (int i = tid; i < 128 * 128; i += 256) {
        int k = i >> 7, n = i & 127;
        float w = __ldg(&W2[i]);
        __nv_bfloat16 hi = __float2bfloat16(w);
        __nv_bfloat16 lo = __float2bfloat16(w - __bfloat162float(hi));
        *(__nv_bfloat16*)(sIhi + n * RSB2 + k * 2) = hi;
        *(__nv_bfloat16*)(sIlo + n * RSB2 + k * 2) = lo;
    }
    if (tid < 128) sRow[tid] = 0.f;
    __syncthreads();
    {
        int r = lane & 7, mat = (lane >> 3) & 1;
        #pragma unroll
        for (int j = 0; j < 2; j++) {
            int n = wid * 16 + j * 8 + r;
            #pragma unroll
            for (int c = 0; c < 8; c++) {
                uint32_t off = (uint32_t)n * RSB2 + c * 32 + mat * 16;
                ldmatrix_x2(B2hi[c][j], uIhi + off);
                ldmatrix_x2(B2lo[c][j], uIlo + off);
            }
        }
    }
    __syncthreads();

    // Per-thread bias and Wfc scalars (cols fixed for the whole kernel)
    const int c0 = wid * 16 + (lane & 3) * 2;
    const float b1s00 = __ldg(&b1[c0]),     b1s01 = __ldg(&b1[c0 + 1]);
    const float b1s10 = __ldg(&b1[c0 + 8]), b1s11 = __ldg(&b1[c0 + 9]);
    const float b2s00 = __ldg(&b2[c0]),     b2s01 = __ldg(&b2[c0 + 1]);
    const float b2s10 = __ldg(&b2[c0 + 8]), b2s11 = __ldg(&b2[c0 + 9]);
    float wf00 = 0.f, wf01 = 0.f, wf10 = 0.f, wf11 = 0.f;
    if (POOL) {
        wf00 = __ldg(&Wfc[c0]);     wf01 = __ldg(&Wfc[c0 + 1]);
        wf10 = __ldg(&Wfc[c0 + 8]); wf11 = __ldg(&Wfc[c0 + 9]);
    }

    // ldmatrix.x4 lane address pattern for A (row-major 16x16)
    const int ar = (lane & 7) + ((lane & 8) ? 8 : 0);
    const int ak = (lane & 16) ? 16 : 0;

    for (int tile = blockIdx.x; tile < ntiles; tile += gridDim.x) {
        const int base = tile * 128;

        // ---- 1) Copy pre-split A planes into smem (uint2 = 4 bf16) ----
        for (int i = tid; i < 128 * KW4; i += 256) {
            int row = i / KW4;
            int j   = i - row * KW4;          // uint2 index within row
            int n   = base + row;
            uint2 hp = make_uint2(0u, 0u), lp = make_uint2(0u, 0u);
            if (n < NN) {
                hp = __ldg((const uint2*)(aggHi + (size_t)n * (K / 2)) + j);
                lp = __ldg((const uint2*)(aggLo + (size_t)n * (K / 2)) + j);
            }
            *(uint2*)(sAhi + row * RSB1 + j * 8) = hp;
            *(uint2*)(sAlo + row * RSB1 + j * 8) = lp;
        }
        __syncthreads();

        // ---- 2) GEMM1 (m-tile pairs) -> relu -> split -> sI ----
        #pragma unroll
        for (int mp = 0; mp < 4; mp++) {
            float acc[2][2][4];
            #pragma unroll
            for (int t = 0; t < 2; t++)
                #pragma unroll
                for (int j = 0; j < 2; j++)
                    #pragma unroll
                    for (int q = 0; q < 4; q++) acc[t][j][q] = 0.f;

            #pragma unroll
            for (int c = 0; c < KCH1; c++) {
                #pragma unroll
                for (int t = 0; t < 2; t++) {
                    uint32_t arow = (uint32_t)(mp * 32 + t * 16 + ar) * RSB1 + ak + c * 32;
                    uint32_t ahi[4], alo[4];
                    ldmatrix_x4(ahi, uAhi + arow);
                    ldmatrix_x4(alo, uAlo + arow);
                    #pragma unroll
                    for (int j = 0; j < 2; j++) {
                        mma_16816(acc[t][j], ahi, B1hi[c][j]);
                        mma_16816(acc[t][j], ahi, B1lo[c][j]);
                        mma_16816(acc[t][j], alo, B1hi[c][j]);
                    }
                }
            }
            #pragma unroll
            for (int t = 0; t < 2; t++) {
                int r0 = mp * 32 + t * 16 + (lane >> 2);
                int r1 = r0 + 8;
                #pragma unroll
                for (int j = 0; j < 2; j++) {
                    float bx = j ? b1s10 : b1s00;
                    float by = j ? b1s11 : b1s01;
                    int cc = wid * 16 + j * 8 + (lane & 3) * 2;
                    float v0 = fmaxf(acc[t][j][0] + bx, 0.f);
                    float v1 = fmaxf(acc[t][j][1] + by, 0.f);
                    float v2 = fmaxf(acc[t][j][2] + bx, 0.f);
                    float v3 = fmaxf(acc[t][j][3] + by, 0.f);
                    uint32_t hp, lp;
                    split2(v0, v1, hp, lp);
                    *(uint32_t*)(sIhi + r0 * RSB2 + cc * 2) = hp;
                    *(uint32_t*)(sIlo + r0 * RSB2 + cc * 2) = lp;
                    split2(v2, v3, hp, lp);
                    *(uint32_t*)(sIhi + r1 * RSB2 + cc * 2) = hp;
                    *(uint32_t*)(sIlo + r1 * RSB2 + cc * 2) = lp;
                }
            }
        }
        __syncthreads();

        // ---- 3) GEMM2 (m-tile pairs) -> bias+relu -> gmem or pool ----
        #pragma unroll
        for (int mp = 0; mp < 4; mp++) {
            float acc[2][2][4];
            #pragma unroll
            for (int t = 0; t < 2; t++)
                #pragma unroll
                for (int j = 0; j < 2; j++)
                    #pragma unroll
                    for (int q = 0; q < 4; q++) acc[t][j][q] = 0.f;

            #pragma unroll
            for (int c = 0; c < 8; c++) {
                #pragma unroll
                for (int t = 0; t < 2; t++) {
                    uint32_t arow = (uint32_t)(mp * 32 + t * 16 + ar) * RSB2 + ak + c * 32;
                    uint32_t ahi[4], alo[4];
                    ldmatrix_x4(ahi, uIhi + arow);
                    ldmatrix_x4(alo, uIlo + arow);
                    #pragma unroll
                    for (int j = 0; j < 2; j++) {
                        mma_16816(acc[t][j], ahi, B2hi[c][j]);
                        mma_16816(acc[t][j], ahi, B2lo[c][j]);
                        mma_16816(acc[t][j], alo, B2hi[c][j]);
                    }
                }
            }
            #pragma unroll
            for (int t = 0; t < 2; t++) {
                int rl0 = mp * 32 + t * 16 + (lane >> 2);
                int rl1 = rl0 + 8;
                if (POOL) {
                    float p0 = 0.f, p1 = 0.f;
                    #pragma unroll
                    for (int j = 0; j < 2; j++) {
                        float bx = j ? b2s10 : b2s00;
                        float by = j ? b2s11 : b2s01;
                        float wx = j ? wf10 : wf00;
                        float wy = j ? wf11 : wf01;
                        p0 += fmaxf(acc[t][j][0] + bx, 0.f) * wx
                            + fmaxf(acc[t][j][1] + by, 0.f) * wy;
                        p1 += fmaxf(acc[t][j][2] + bx, 0.f) * wx
                            + fmaxf(acc[t][j][3] + by, 0.f) * wy;
                    }
                    // reduce over the 4 lanes sharing each row (lane&3)
                    p0 += __shfl_xor_sync(0xffffffffu, p0, 1);
                    p0 += __shfl_xor_sync(0xffffffffu, p0, 2);
                    p1 += __shfl_xor_sync(0xffffffffu, p1, 1);
                    p1 += __shfl_xor_sync(0xffffffffu, p1, 2);
                    if ((lane & 3) == 0) {
                        atomicAdd(&sRow[rl0], p0);
                        atomicAdd(&sRow[rl1], p1);
                    }
                } else {
                    int r0 = base + rl0;
                    int r1 = base + rl1;
                    #pragma unroll
                    for (int j = 0; j < 2; j++) {
                        float bx = j ? b2s10 : b2s00;
                        float by = j ? b2s11 : b2s01;
                        int cc = wid * 16 + j * 8 + (lane & 3) * 2;
                        if (r0 < NN) {
                            float2 o;
                            o.x = fmaxf(acc[t][j][0] + bx, 0.f);
                            o.y = fmaxf(acc[t][j][1] + by, 0.f);
                            *(float2*)(out + (size_t)r0 * 128 + cc) = o;
                        }
                        if (r1 < NN) {
                            float2 o;
                            o.x = fmaxf(acc[t][j][2] + bx, 0.f);
                            o.y = fmaxf(acc[t][j][3] + by, 0.f);
                            *(float2*)(out + (size_t)r1 * 128 + cc) = o;
                        }
                    }
                }
            }
        }
        if (POOL) {
            __syncthreads();
            for (int r = tid; r < 128; r += 256) {
                int n = base + r;
                if (n < NN) {
                    float v = sRow[r];
                    atomicAdd(&g_gsum[__ldg(&batch[n])], v);
                }
                sRow[r] = 0.f;
            }
        }
        __syncthreads();   // sA/sI (and sRow) ready before next tile
    }
}

// ===========================================================================
// counts per graph via binary search on the SORTED batch array
__global__ void finalize(const int* __restrict__ batch,
                         float* __restrict__ out, const float* __restrict__ bfc) {
    int g = threadIdx.x;
    if (g >= GG) return;
    int lo = 0, hi = NN;
    while (lo < hi) { int m = (lo + hi) >> 1; if (__ldg(&batch[m]) < g) lo = m + 1; else hi = m; }
    int lb = lo;
    lo = 0; hi = NN;
    while (lo < hi) { int m = (lo + hi) >> 1; if (__ldg(&batch[m]) < g + 1) lo = m + 1; else hi = m; }
    int cnt = lo - lb;
    out[g] = g_gsum[g] / fmaxf((float)cnt, 1.0f) + bfc[0];
}

// ===========================================================================
extern "C" void kernel_launch(void* const* d_in, const int* in_sizes, int n_in,
                              void* d_out, int out_size) {
    const float* x     = (const float*)d_in[0];
    const int*   ei    = (const int*)d_in[1];     // int32
    const int*   batch = (const int*)d_in[2];     // int32 (sorted)
    const float* W1a = (const float*)d_in[3];
    const float* b1a = (const float*)d_in[4];
    const float* W1b = (const float*)d_in[5];
    const float* b1b = (const float*)d_in[6];
    const float* W2a = (const float*)d_in[7];
    const float* b2a = (const float*)d_in[8];
    const float* W2b = (const float*)d_in[9];
    const float* b2b = (const float*)d_in[10];
    const float* Wfc = (const float*)d_in[11];
    const float* bfc = (const float*)d_in[12];
    float* out = (float*)d_out;

    const int* esrc = ei;
    const int* edst = ei + EE;

    float *h1;
    uint32_t *aggHi, *aggLo;
    cudaGetSymbolAddress((void**)&h1, g_h1);
    cudaGetSymbolAddress((void**)&aggHi, g_aggHi);
    cudaGetSymbolAddress((void**)&aggLo, g_aggLo);

    const int smemF64  = 2 * 128 * (64 * 2 + 16) + 2 * 128 * (128 * 2 + 16);   // 106,496
    const int smemF128 = 4 * 128 * (128 * 2 + 16);                             // 139,264
    cudaFuncSetAttribute(fused_pair<64, false>,  cudaFuncAttributeMaxDynamicSharedMemorySize, smemF64);
    cudaFuncSetAttribute(fused_pair<128, true>,  cudaFuncAttributeMaxDynamicSharedMemorySize, smemF128);

    const int ntiles = (NN + 127) / 128;   // 782
    const int e4blocks = (EE / 4 + 255) / 256;   // 1563

    // ---- CSR build (per call; reused by both layers) ----
    zero_cnt<<<(NN + 255) / 256, 256>>>();
    hist_kernel<<<e4blocks, 256>>>(edst);
    scan_kernel<<<1, SCAN_T>>>();
    reorder_kernel<<<e4blocks, 256>>>(esrc, edst);

    // ---- Layer 1 (writes h1) ----
    gather_split_64<<<1024, 256>>>(x);
    fused_pair<64, false><<<148, 256, smemF64>>>(aggHi, aggLo, W1a, b1a, W1b, b1b,
                                                 h1, nullptr, nullptr, ntiles);

    // ---- Layer 2 (pool fused into epilogue; writes only g_gsum) ----
    gather_split_128<<<1024, 256>>>(h1);
    fused_pair<128, true><<<148, 256, smemF128>>>(aggHi, aggLo, W2a, b2a, W2b, b2b,
                                                  nullptr, batch, Wfc, ntiles);

    // ---- Finalize (counts via binary search on sorted batch) ----
    finalize<<<1, 256>>>(batch, out, bfc);
}

// round 14
// speedup vs baseline: 1.1356x; 1.1356x over previous
#include <cuda_runtime.h>
#include <cuda_bf16.h>
#include <cstdint>

constexpr int NN  = 100000;   // nodes
constexpr int EE  = 1600000;  // edges
constexpr int GG  = 256;      // graphs
constexpr int DIN = 64;
constexpr int HID = 128;

// Scratch (device globals — no allocation allowed)
__device__ uint32_t g_aggHi[(size_t)NN * 64];   // packed bf16x2 hi plane (K<=128)
__device__ uint32_t g_aggLo[(size_t)NN * 64];   // packed bf16x2 lo plane
__device__ float g_h1 [(size_t)NN * HID];
__device__ float g_gsum[GG];
// CSR scratch
__device__ int g_cnt [NN];
__device__ int g_off [NN];
__device__ int g_pos [EE];
__device__ int g_ssrc[EE];

// ===========================================================================
// Warp-level tensor-core + async-copy primitives (base ISA on target sm_100)
// ===========================================================================
__device__ __forceinline__ uint32_t smem_u32(const void* p) {
    uint32_t a;
    asm("{ .reg .u64 t; cvta.to.shared.u64 t, %1; cvt.u32.u64 %0, t; }" : "=r"(a) : "l"(p));
    return a;
}

__device__ __forceinline__ void ldmatrix_x4(uint32_t* r, uint32_t addr) {
    asm volatile("ldmatrix.sync.aligned.m8n8.x4.shared.b16 {%0,%1,%2,%3}, [%4];"
                 : "=r"(r[0]), "=r"(r[1]), "=r"(r[2]), "=r"(r[3]) : "r"(addr));
}
__device__ __forceinline__ void ldmatrix_x2(uint32_t* r, uint32_t addr) {
    asm volatile("ldmatrix.sync.aligned.m8n8.x2.shared.b16 {%0,%1}, [%2];"
                 : "=r"(r[0]), "=r"(r[1]) : "r"(addr));
}

// D(16x8,f32) += A(16x16,bf16,row) * B(16x8,bf16,col)
__device__ __forceinline__ void mma_16816(float* d, const uint32_t* a, const uint32_t* b) {
    asm volatile(
        "mma.sync.aligned.m16n8k16.row.col.f32.bf16.bf16.f32 "
        "{%0,%1,%2,%3}, {%4,%5,%6,%7}, {%8,%9}, {%0,%1,%2,%3};"
        : "+f"(d[0]), "+f"(d[1]), "+f"(d[2]), "+f"(d[3])
        : "r"(a[0]), "r"(a[1]), "r"(a[2]), "r"(a[3]), "r"(b[0]), "r"(b[1]));
}

// Split two floats into packed bf16x2 hi and lo words
__device__ __forceinline__ void split2(float x, float y, uint32_t& hp, uint32_t& lp) {
    __nv_bfloat16 hx = __float2bfloat16(x), hy = __float2bfloat16(y);
    __nv_bfloat16 lx = __float2bfloat16(x - __bfloat162float(hx));
    __nv_bfloat16 ly = __float2bfloat16(y - __bfloat162float(hy));
    hp = ((uint32_t)__bfloat16_as_ushort(hy) << 16) | __bfloat16_as_ushort(hx);
    lp = ((uint32_t)__bfloat16_as_ushort(ly) << 16) | __bfloat16_as_ushort(lx);
}

__device__ __forceinline__ void cp_async16(uint32_t saddr, const void* gaddr, int srcsz) {
    asm volatile("cp.async.cg.shared.global [%0], [%1], 16, %2;"
                 :: "r"(saddr), "l"(gaddr), "r"(srcsz) : "memory");
}
#define CP_COMMIT() asm volatile("cp.async.commit_group;" ::: "memory")
#define CP_WAIT1()  asm volatile("cp.async.wait_group 1;" ::: "memory")

// ===========================================================================
// CSR build (R12 version): zero -> histogram(+slot) -> scan -> reorder
// ===========================================================================
__global__ void zero_cnt() {
    int t = blockIdx.x * blockDim.x + threadIdx.x;
    if (t < NN) g_cnt[t] = 0;
    if (t < GG) g_gsum[t] = 0.f;
}

__global__ void hist_kernel(const int* __restrict__ dst) {
    int e = blockIdx.x * blockDim.x + threadIdx.x;
    if (e < EE) g_pos[e] = atomicAdd(&g_cnt[__ldg(&dst[e])], 1);
}

constexpr int SCAN_T  = 1024;
constexpr int SCAN_CH = (NN + SCAN_T - 1) / SCAN_T;   // 98

__global__ void scan_kernel() {
    __shared__ int ssum[SCAN_T];
    int t = threadIdx.x;
    int base = t * SCAN_CH;
    int s = 0;
    #pragma unroll 4
    for (int i = 0; i < SCAN_CH; i++) {
        int j = base + i;
        if (j < NN) s += g_cnt[j];
    }
    ssum[t] = s;
    __syncthreads();
    for (int d = 1; d < SCAN_T; d <<= 1) {
        int v = (t >= d) ? ssum[t - d] : 0;
        __syncthreads();
        ssum[t] += v;
        __syncthreads();
    }
    int run = (t > 0) ? ssum[t - 1] : 0;
    for (int i = 0; i < SCAN_CH; i++) {
        int j = base + i;
        if (j < NN) { g_off[j] = run; run += g_cnt[j]; }
    }
}

__global__ void reorder_kernel(const int* __restrict__ src,
                               const int* __restrict__ dst) {
    int e = blockIdx.x * blockDim.x + threadIdx.x;
    if (e < EE) {
        int d = __ldg(&dst[e]);
        g_ssrc[g_off[d] + g_pos[e]] = __ldg(&src[e]);
    }
}

// ===========================================================================
// Gather aggregation (R12 versions) -> bf16 hi/lo planes
// ===========================================================================
__global__ void gather_split_64(const float* __restrict__ x) {
    int gw   = (blockIdx.x * blockDim.x + threadIdx.x) >> 5;
    int lane = threadIdx.x & 31;
    int nw   = (gridDim.x * blockDim.x) >> 5;
    for (int n = gw; n < NN; n += nw) {
        int lo = g_off[n], deg = g_cnt[n];
        float2 acc = __ldg((const float2*)(x + (size_t)n * 64) + lane);
        int i = 0;
        for (; i + 3 < deg; i += 4) {
            int s0 = __ldg(&g_ssrc[lo + i]);
            int s1 = __ldg(&g_ssrc[lo + i + 1]);
            int s2 = __ldg(&g_ssrc[lo + i + 2]);
            int s3 = __ldg(&g_ssrc[lo + i + 3]);
            float2 v0 = __ldg((const float2*)(x + (size_t)s0 * 64) + lane);
            float2 v1 = __ldg((const float2*)(x + (size_t)s1 * 64) + lane);
            float2 v2 = __ldg((const float2*)(x + (size_t)s2 * 64) + lane);
            float2 v3 = __ldg((const float2*)(x + (size_t)s3 * 64) + lane);
            acc.x += v0.x + v1.x + v2.x + v3.x;
            acc.y += v0.y + v1.y + v2.y + v3.y;
        }
        for (; i < deg; i++) {
            int s = __ldg(&g_ssrc[lo + i]);
            float2 v = __ldg((const float2*)(x + (size_t)s * 64) + lane);
            acc.x += v.x; acc.y += v.y;
        }
        uint32_t hp, lp;
        split2(acc.x, acc.y, hp, lp);
        g_aggHi[(size_t)n * 32 + lane] = hp;
        g_aggLo[(size_t)n * 32 + lane] = lp;
    }
}

__global__ void gather_split_128(const float* __restrict__ x) {
    int gw   = (blockIdx.x * blockDim.x + threadIdx.x) >> 5;
    int lane = threadIdx.x & 31;
    int nw   = (gridDim.x * blockDim.x) >> 5;
    for (int n = gw; n < NN; n += nw) {
        int lo = g_off[n], deg = g_cnt[n];
        float4 acc = __ldg((const float4*)(x + (size_t)n * 128) + lane);
        int i = 0;
        for (; i + 3 < deg; i += 4) {
            int s0 = __ldg(&g_ssrc[lo + i]);
            int s1 = __ldg(&g_ssrc[lo + i + 1]);
            int s2 = __ldg(&g_ssrc[lo + i + 2]);
            int s3 = __ldg(&g_ssrc[lo + i + 3]);
            float4 v0 = __ldg((const float4*)(x + (size_t)s0 * 128) + lane);
            float4 v1 = __ldg((const float4*)(x + (size_t)s1 * 128) + lane);
            float4 v2 = __ldg((const float4*)(x + (size_t)s2 * 128) + lane);
            float4 v3 = __ldg((const float4*)(x + (size_t)s3 * 128) + lane);
            acc.x += v0.x + v1.x + v2.x + v3.x;
            acc.y += v0.y + v1.y + v2.y + v3.y;
            acc.z += v0.z + v1.z + v2.z + v3.z;
            acc.w += v0.w + v1.w + v2.w + v3.w;
        }
        for (; i < deg; i++) {
            int s = __ldg(&g_ssrc[lo + i]);
            float4 v = __ldg((const float4*)(x + (size_t)s * 128) + lane);
            acc.x += v.x; acc.y += v.y; acc.z += v.z; acc.w += v.w;
        }
        uint2 hp, lp;
        split2(acc.x, acc.y, hp.x, lp.x);
        split2(acc.z, acc.w, hp.y, lp.y);
        *(uint2*)(g_aggHi + (size_t)n * 64 + lane * 2) = hp;
        *(uint2*)(g_aggLo + (size_t)n * 64 + lane * 2) = lp;
    }
}

// ===========================================================================
// Fused GEMM pair with cp.async double-buffered A staging.
// out = relu(relu(A@W1+b1)@W2+b2); POOL folds mean-pool + FC into epilogue.
// ===========================================================================
template <int K, bool POOL>
__global__ __launch_bounds__(256, 1)
void fused_pair(const uint32_t* __restrict__ aggHi, const uint32_t* __restrict__ aggLo,
                const float* __restrict__ W1, const float* __restrict__ b1,
                const float* __restrict__ W2, const float* __restrict__ b2,
                float* __restrict__ out,
                const int* __restrict__ batch, const float* __restrict__ Wfc,
                int ntiles)
{
    constexpr int KCH1 = K / 16;          // k-chunks of GEMM1
    constexpr int RSB1 = K * 2 + 16;      // sA row stride bytes (conflict-free, /16)
    constexpr int RSB2 = 128 * 2 + 16;    // sI row stride bytes
    constexpr int CH   = K * 2 / 16;      // 16B chunks per row per plane
    constexpr int ABUF = 128 * RSB1;      // one plane
    extern __shared__ __align__(16) char smem[];
    char* sA[2][2];                       // [buf][hi/lo]
    sA[0][0] = smem;
    sA[0][1] = smem + ABUF;
    sA[1][0] = smem + 2 * ABUF;
    sA[1][1] = smem + 3 * ABUF;
    char* sIhi = smem + 4 * ABUF;
    char* sIlo = sIhi + 128 * RSB2;
    __shared__ float sRow[128];

    const int tid  = threadIdx.x;
    const int wid  = tid >> 5;
    const int lane = tid & 31;
    const uint32_t uIhi = smem_u32(sIhi), uIlo = smem_u32(sIlo);
    const uint32_t uA00 = smem_u32(sA[0][0]);   // buf0 hi base; others by offset

    // ---- async stage of one tile's A planes into buffer b ----
    auto stage = [&](int tile, int b) {
        const int base = tile * 128;
        uint32_t sh = uA00 + (uint32_t)(2 * b) * ABUF;       // hi plane of buf b
        uint32_t sl = sh + ABUF;                              // lo plane
        for (int i = tid; i < 128 * CH; i += 256) {
            int row = i / CH;
            int j   = i - row * CH;
            int n   = base + row;
            bool v  = n < NN;
            int nc  = v ? n : 0;
            const char* gh = (const char*)(aggHi + (size_t)nc * (K / 2)) + j * 16;
            const char* gl = (const char*)(aggLo + (size_t)nc * (K / 2)) + j * 16;
            uint32_t so = (uint32_t)row * RSB1 + j * 16;
            cp_async16(sh + so, gh, v ? 16 : 0);
            cp_async16(sl + so, gl, v ? 16 : 0);
        }
    };

    // ---- Prologue: kick off tile-0 copy, overlapping with weight staging ----
    int tile0 = blockIdx.x;
    if (tile0 < ntiles) stage(tile0, 0);
    CP_COMMIT();

    // ---- Stage W1^T hi/lo into sI (temp), extract B1 fragments ----
    uint32_t B1hi[KCH1][2][2], B1lo[KCH1][2][2];
    for (int i = tid; i < K * 128; i += 256) {
        int k = i >> 7, n = i & 127;                  // W1[k][n], coalesced
        float w = __ldg(&W1[i]);
        __nv_bfloat16 hi = __float2bfloat16(w);
        __nv_bfloat16 lo = __float2bfloat16(w - __bfloat162float(hi));
        *(__nv_bfloat16*)(sIhi + n * RSB1 + k * 2) = hi;
        *(__nv_bfloat16*)(sIlo + n * RSB1 + k * 2) = lo;
    }
    __syncthreads();
    {
        int r = lane & 7, mat = (lane >> 3) & 1;
        #pragma unroll
        for (int j = 0; j < 2; j++) {
            int n = wid * 16 + j * 8 + r;
            #pragma unroll
            for (int c = 0; c < KCH1; c++) {
                uint32_t off = (uint32_t)n * RSB1 + c * 32 + mat * 16;
                ldmatrix_x2(B1hi[c][j], uIhi + off);
                ldmatrix_x2(B1lo[c][j], uIlo + off);
            }
        }
    }
    __syncthreads();

    // ---- Stage W2^T hi/lo into sI (temp), extract B2 fragments ----
    uint32_t B2hi[8][2][2], B2lo[8][2][2];
    for (int i = tid; i < 128 * 128; i += 256) {
        int k = i >> 7, n = i & 127;
        float w = __ldg(&W2[i]);
        __nv_bfloat16 hi = __float2bfloat16(w);
        __nv_bfloat16 lo = __float2bfloat16(w - __bfloat162float(hi));
        *(__nv_bfloat16*)(sIhi + n * RSB2 + k * 2) = hi;
        *(__nv_bfloat16*)(sIlo + n * RSB2 + k * 2) = lo;
    }
    if (tid < 128) sRow[tid] = 0.f;
    __syncthreads();
    {
        int r = lane & 7, mat = (lane >> 3) & 1;
        #pragma unroll
        for (int j = 0; j < 2; j++) {
            int n = wid * 16 + j * 8 + r;
            #pragma unroll
            for (int c = 0; c < 8; c++) {
                uint32_t off = (uint32_t)n * RSB2 + c * 32 + mat * 16;
                ldmatrix_x2(B2hi[c][j], uIhi + off);
                ldmatrix_x2(B2lo[c][j], uIlo + off);
            }
        }
    }
    __syncthreads();

    // Per-thread bias and Wfc scalars (cols fixed for the whole kernel)
    const int c0 = wid * 16 + (lane & 3) * 2;
    const float b1s00 = __ldg(&b1[c0]),     b1s01 = __ldg(&b1[c0 + 1]);
    const float b1s10 = __ldg(&b1[c0 + 8]), b1s11 = __ldg(&b1[c0 + 9]);
    const float b2s00 = __ldg(&b2[c0]),     b2s01 = __ldg(&b2[c0 + 1]);
    const float b2s10 = __ldg(&b2[c0 + 8]), b2s11 = __ldg(&b2[c0 + 9]);
    float wf00 = 0.f, wf01 = 0.f, wf10 = 0.f, wf11 = 0.f;
    if (POOL) {
        wf00 = __ldg(&Wfc[c0]);     wf01 = __ldg(&Wfc[c0 + 1]);
        wf10 = __ldg(&Wfc[c0 + 8]); wf11 = __ldg(&Wfc[c0 + 9]);
    }

    // ldmatrix.x4 lane address pattern for A (row-major 16x16)
    const int ar = (lane & 7) + ((lane & 8) ? 8 : 0);
    const int ak = (lane & 16) ? 16 : 0;

    int bsel = 0;
    for (int tile = tile0; tile < ntiles; tile += gridDim.x) {
        const int base = tile * 128;

        // ---- Prefetch next tile into the other buffer, then wait on current ----
        int nxt = tile + gridDim.x;
        if (nxt < ntiles) stage(nxt, bsel ^ 1);
        CP_COMMIT();
        CP_WAIT1();
        __syncthreads();

        const uint32_t uAhi = uA00 + (uint32_t)(2 * bsel) * ABUF;
        const uint32_t uAlo = uAhi + ABUF;

        // ---- GEMM1 (m-tile pairs) -> relu -> split -> sI ----
        #pragma unroll
        for (int mp = 0; mp < 4; mp++) {
            float acc[2][2][4];
            #pragma unroll
            for (int t = 0; t < 2; t++)
                #pragma unroll
                for (int j = 0; j < 2; j++)
                    #pragma unroll
                    for (int q = 0; q < 4; q++) acc[t][j][q] = 0.f;

            #pragma unroll
            for (int c = 0; c < KCH1; c++) {
                #pragma unroll
                for (int t = 0; t < 2; t++) {
                    uint32_t arow = (uint32_t)(mp * 32 + t * 16 + ar) * RSB1 + ak + c * 32;
                    uint32_t ahi[4], alo[4];
                    ldmatrix_x4(ahi, uAhi + arow);
                    ldmatrix_x4(alo, uAlo + arow);
                    #pragma unroll
                    for (int j = 0; j < 2; j++) {
                        mma_16816(acc[t][j], ahi, B1hi[c][j]);
                        mma_16816(acc[t][j], ahi, B1lo[c][j]);
                        mma_16816(acc[t][j], alo, B1hi[c][j]);
                    }
                }
            }
            #pragma unroll
            for (int t = 0; t < 2; t++) {
                int r0 = mp * 32 + t * 16 + (lane >> 2);
                int r1 = r0 + 8;
                #pragma unroll
                for (int j = 0; j < 2; j++) {
                    float bx = j ? b1s10 : b1s00;
                    float by = j ? b1s11 : b1s01;
                    int cc = wid * 16 + j * 8 + (lane & 3) * 2;
                    float v0 = fmaxf(acc[t][j][0] + bx, 0.f);
                    float v1 = fmaxf(acc[t][j][1] + by, 0.f);
                    float v2 = fmaxf(acc[t][j][2] + bx, 0.f);
                    float v3 = fmaxf(acc[t][j][3] + by, 0.f);
                    uint32_t hp, lp;
                    split2(v0, v1, hp, lp);
                    *(uint32_t*)(sIhi + r0 * RSB2 + cc * 2) = hp;
                    *(uint32_t*)(sIlo + r0 * RSB2 + cc * 2) = lp;
                    split2(v2, v3, hp, lp);
                    *(uint32_t*)(sIhi + r1 * RSB2 + cc * 2) = hp;
                    *(uint32_t*)(sIlo + r1 * RSB2 + cc * 2) = lp;
                }
            }
        }
        __syncthreads();

        // ---- GEMM2 (m-tile pairs) -> bias+relu -> gmem or pool ----
        #pragma unroll
        for (int mp = 0; mp < 4; mp++) {
            float acc[2][2][4];
            #pragma unroll
            for (int t = 0; t < 2; t++)
                #pragma unroll
                for (int j = 0; j < 2; j++)
                    #pragma unroll
                    for (int q = 0; q < 4; q++) acc[t][j][q] = 0.f;

            #pragma unroll
            for (int c = 0; c < 8; c++) {
                #pragma unroll
                for (int t = 0; t < 2; t++) {
                    uint32_t arow = (uint32_t)(mp * 32 + t * 16 + ar) * RSB2 + ak + c * 32;
                    uint32_t ahi[4], alo[4];
                    ldmatrix_x4(ahi, uIhi + arow);
                    ldmatrix_x4(alo, uIlo + arow);
                    #pragma unroll
                    for (int j = 0; j < 2; j++) {
                        mma_16816(acc[t][j], ahi, B2hi[c][j]);
                        mma_16816(acc[t][j], ahi, B2lo[c][j]);
                        mma_16816(acc[t][j], alo, B2hi[c][j]);
                    }
                }
            }
            #pragma unroll
            for (int t = 0; t < 2; t++) {
                int rl0 = mp * 32 + t * 16 + (lane >> 2);
                int rl1 = rl0 + 8;
                if (POOL) {
                    float p0 = 0.f, p1 = 0.f;
                    #pragma unroll
                    for (int j = 0; j < 2; j++) {
                        float bx = j ? b2s10 : b2s00;
                        float by = j ? b2s11 : b2s01;
                        float wx = j ? wf10 : wf00;
                        float wy = j ? wf11 : wf01;
                        p0 += fmaxf(acc[t][j][0] + bx, 0.f) * wx
                            + fmaxf(acc[t][j][1] + by, 0.f) * wy;
                        p1 += fmaxf(acc[t][j][2] + bx, 0.f) * wx
                            + fmaxf(acc[t][j][3] + by, 0.f) * wy;
                    }
                    p0 += __shfl_xor_sync(0xffffffffu, p0, 1);
                    p0 += __shfl_xor_sync(0xffffffffu, p0, 2);
                    p1 += __shfl_xor_sync(0xffffffffu, p1, 1);
                    p1 += __shfl_xor_sync(0xffffffffu, p1, 2);
                    if ((lane & 3) == 0) {
                        atomicAdd(&sRow[rl0], p0);
                        atomicAdd(&sRow[rl1], p1);
                    }
                } else {
                    int r0 = base + rl0;
                    int r1 = base + rl1;
                    #pragma unroll
                    for (int j = 0; j < 2; j++) {
                        float bx = j ? b2s10 : b2s00;
                        float by = j ? b2s11 : b2s01;
                        int cc = wid * 16 + j * 8 + (lane & 3) * 2;
                        if (r0 < NN) {
                            float2 o;
                            o.x = fmaxf(acc[t][j][0] + bx, 0.f);
                            o.y = fmaxf(acc[t][j][1] + by, 0.f);
                            *(float2*)(out + (size_t)r0 * 128 + cc) = o;
                        }
                        if (r1 < NN) {
                            float2 o;
                            o.x = fmaxf(acc[t][j][2] + bx, 0.f);
                            o.y = fmaxf(acc[t][j][3] + by, 0.f);
                            *(float2*)(out + (size_t)r1 * 128 + cc) = o;
                        }
                    }
                }
            }
        }
        if (POOL) {
            __syncthreads();
            for (int r = tid; r < 128; r += 256) {
                int n = base + r;
                if (n < NN) {
                    float v = sRow[r];
                    atomicAdd(&g_gsum[__ldg(&batch[n])], v);
                }
                sRow[r] = 0.f;
            }
        }
        __syncthreads();   // buf[bsel] reads + sI/sRow complete before reuse
        bsel ^= 1;
    }
}

// ===========================================================================
// counts per graph via binary search on the SORTED batch array
__global__ void finalize(const int* __restrict__ batch,
                         float* __restrict__ out, const float* __restrict__ bfc) {
    int g = threadIdx.x;
    if (g >= GG) return;
    int lo = 0, hi = NN;
    while (lo < hi) { int m = (lo + hi) >> 1; if (__ldg(&batch[m]) < g) lo = m + 1; else hi = m; }
    int lb = lo;
    lo = 0; hi = NN;
    while (lo < hi) { int m = (lo + hi) >> 1; if (__ldg(&batch[m]) < g + 1) lo = m + 1; else hi = m; }
    int cnt = lo - lb;
    out[g] = g_gsum[g] / fmaxf((float)cnt, 1.0f) + bfc[0];
}

// ===========================================================================
extern "C" void kernel_launch(void* const* d_in, const int* in_sizes, int n_in,
                              void* d_out, int out_size) {
    const float* x     = (const float*)d_in[0];
    const int*   ei    = (const int*)d_in[1];     // int32
    const int*   batch = (const int*)d_in[2];     // int32 (sorted)
    const float* W1a = (const float*)d_in[3];
    const float* b1a = (const float*)d_in[4];
    const float* W1b = (const float*)d_in[5];
    const float* b1b = (const float*)d_in[6];
    const float* W2a = (const float*)d_in[7];
    const float* b2a = (const float*)d_in[8];
    const float* W2b = (const float*)d_in[9];
    const float* b2b = (const float*)d_in[10];
    const float* Wfc = (const float*)d_in[11];
    const float* bfc = (const float*)d_in[12];
    float* out = (float*)d_out;

    const int* esrc = ei;
    const int* edst = ei + EE;

    float *h1;
    uint32_t *aggHi, *aggLo;
    cudaGetSymbolAddress((void**)&h1, g_h1);
    cudaGetSymbolAddress((void**)&aggHi, g_aggHi);
    cudaGetSymbolAddress((void**)&aggLo, g_aggLo);

    // smem: 4 A-planes (double-buffered hi/lo) + sI hi/lo
    const int smemF64  = 4 * 128 * (64 * 2 + 16) + 2 * 128 * (128 * 2 + 16);   // 143,360
    const int smemF128 = 4 * 128 * (128 * 2 + 16) + 2 * 128 * (128 * 2 + 16);  // 208,896
    cudaFuncSetAttribute(fused_pair<64, false>,  cudaFuncAttributeMaxDynamicSharedMemorySize, smemF64);
    cudaFuncSetAttribute(fused_pair<128, true>,  cudaFuncAttributeMaxDynamicSharedMemorySize, smemF128);

    const int ntiles = (NN + 127) / 128;   // 782

    // ---- CSR build (per call; reused by both layers) ----
    zero_cnt<<<(NN + 255) / 256, 256>>>();
    hist_kernel<<<(EE + 255) / 256, 256>>>(edst);
    scan_kernel<<<1, SCAN_T>>>();
    reorder_kernel<<<(EE + 255) / 256, 256>>>(esrc, edst);

    // ---- Layer 1 (writes h1) ----
    gather_split_64<<<1024, 256>>>(x);
    fused_pair<64, false><<<148, 256, smemF64>>>(aggHi, aggLo, W1a, b1a, W1b, b1b,
                                                 h1, nullptr, nullptr, ntiles);

    // ---- Layer 2 (pool fused into epilogue; writes only g_gsum) ----
    gather_split_128<<<1024, 256>>>(h1);
    fused_pair<128, true><<<148, 256, smemF128>>>(aggHi, aggLo, W2a, b2a, W2b, b2b,
                                                  nullptr, batch, Wfc, ntiles);

    // ---- Finalize (counts via binary search on sorted batch) ----
    finalize<<<1, 256>>>(batch, out, bfc);
}

// round 15
// speedup vs baseline: 1.2249x; 1.0786x over previous
#include <cuda_runtime.h>
#include <cuda_bf16.h>
#include <cstdint>

constexpr int NN  = 100000;   // nodes
constexpr int EE  = 1600000;  // edges
constexpr int GG  = 256;      // graphs
constexpr int DIN = 64;
constexpr int HID = 128;

// Scratch (device globals — no allocation allowed)
__device__ uint32_t g_aggHi[(size_t)NN * 64];   // packed bf16x2 hi plane (K<=128)
__device__ uint32_t g_aggLo[(size_t)NN * 64];   // packed bf16x2 lo plane
__device__ uint32_t g_h1b [(size_t)NN * 64];    // h1 as packed bf16x2 [NN][64]
__device__ float g_gsum[GG];
// CSR scratch
__device__ int g_cnt [NN];
__device__ int g_off [NN];
__device__ int g_pos [EE];
__device__ int g_ssrc[EE];

// ===========================================================================
// Warp-level tensor-core + async-copy primitives (base ISA on target sm_100)
// ===========================================================================
__device__ __forceinline__ uint32_t smem_u32(const void* p) {
    uint32_t a;
    asm("{ .reg .u64 t; cvta.to.shared.u64 t, %1; cvt.u32.u64 %0, t; }" : "=r"(a) : "l"(p));
    return a;
}

__device__ __forceinline__ void ldmatrix_x4(uint32_t* r, uint32_t addr) {
    asm volatile("ldmatrix.sync.aligned.m8n8.x4.shared.b16 {%0,%1,%2,%3}, [%4];"
                 : "=r"(r[0]), "=r"(r[1]), "=r"(r[2]), "=r"(r[3]) : "r"(addr));
}
__device__ __forceinline__ void ldmatrix_x2(uint32_t* r, uint32_t addr) {
    asm volatile("ldmatrix.sync.aligned.m8n8.x2.shared.b16 {%0,%1}, [%2];"
                 : "=r"(r[0]), "=r"(r[1]) : "r"(addr));
}

// D(16x8,f32) += A(16x16,bf16,row) * B(16x8,bf16,col)
__device__ __forceinline__ void mma_16816(float* d, const uint32_t* a, const uint32_t* b) {
    asm volatile(
        "mma.sync.aligned.m16n8k16.row.col.f32.bf16.bf16.f32 "
        "{%0,%1,%2,%3}, {%4,%5,%6,%7}, {%8,%9}, {%0,%1,%2,%3};"
        : "+f"(d[0]), "+f"(d[1]), "+f"(d[2]), "+f"(d[3])
        : "r"(a[0]), "r"(a[1]), "r"(a[2]), "r"(a[3]), "r"(b[0]), "r"(b[1]));
}

// Split two floats into packed bf16x2 hi and lo words
__device__ __forceinline__ void split2(float x, float y, uint32_t& hp, uint32_t& lp) {
    __nv_bfloat16 hx = __float2bfloat16(x), hy = __float2bfloat16(y);
    __nv_bfloat16 lx = __float2bfloat16(x - __bfloat162float(hx));
    __nv_bfloat16 ly = __float2bfloat16(y - __bfloat162float(hy));
    hp = ((uint32_t)__bfloat16_as_ushort(hy) << 16) | __bfloat16_as_ushort(hx);
    lp = ((uint32_t)__bfloat16_as_ushort(ly) << 16) | __bfloat16_as_ushort(lx);
}

__device__ __forceinline__ uint32_t packbf(float x, float y) {
    __nv_bfloat16 bx = __float2bfloat16(x), by = __float2bfloat16(y);
    return ((uint32_t)__bfloat16_as_ushort(by) << 16) | __bfloat16_as_ushort(bx);
}

// bf16x2 word -> two exact fp32 (bf16 bits << 16)
__device__ __forceinline__ float2 bf2f(uint32_t p) {
    float2 r;
    r.x = __uint_as_float(p << 16);
    r.y = __uint_as_float(p & 0xffff0000u);
    return r;
}

__device__ __forceinline__ void cp_async16(uint32_t saddr, const void* gaddr, int srcsz) {
    asm volatile("cp.async.cg.shared.global [%0], [%1], 16, %2;"
                 :: "r"(saddr), "l"(gaddr), "r"(srcsz) : "memory");
}
#define CP_COMMIT() asm volatile("cp.async.commit_group;" ::: "memory")
#define CP_WAIT1()  asm volatile("cp.async.wait_group 1;" ::: "memory")

// ===========================================================================
// CSR build (R12 version): zero -> histogram(+slot) -> scan -> reorder
// ===========================================================================
__global__ void zero_cnt() {
    int t = blockIdx.x * blockDim.x + threadIdx.x;
    if (t < NN) g_cnt[t] = 0;
    if (t < GG) g_gsum[t] = 0.f;
}

__global__ void hist_kernel(const int* __restrict__ dst) {
    int e = blockIdx.x * blockDim.x + threadIdx.x;
    if (e < EE) g_pos[e] = atomicAdd(&g_cnt[__ldg(&dst[e])], 1);
}

constexpr int SCAN_T  = 1024;
constexpr int SCAN_CH = (NN + SCAN_T - 1) / SCAN_T;   // 98

__global__ void scan_kernel() {
    __shared__ int ssum[SCAN_T];
    int t = threadIdx.x;
    int base = t * SCAN_CH;
    int s = 0;
    #pragma unroll 4
    for (int i = 0; i < SCAN_CH; i++) {
        int j = base + i;
        if (j < NN) s += g_cnt[j];
    }
    ssum[t] = s;
    __syncthreads();
    for (int d = 1; d < SCAN_T; d <<= 1) {
        int v = (t >= d) ? ssum[t - d] : 0;
        __syncthreads();
        ssum[t] += v;
        __syncthreads();
    }
    int run = (t > 0) ? ssum[t - 1] : 0;
    for (int i = 0; i < SCAN_CH; i++) {
        int j = base + i;
        if (j < NN) { g_off[j] = run; run += g_cnt[j]; }
    }
}

__global__ void reorder_kernel(const int* __restrict__ src,
                               const int* __restrict__ dst) {
    int e = blockIdx.x * blockDim.x + threadIdx.x;
    if (e < EE) {
        int d = __ldg(&dst[e]);
        g_ssrc[g_off[d] + g_pos[e]] = __ldg(&src[e]);
    }
}

// ===========================================================================
// Gather aggregation -> bf16 hi/lo planes: agg[n] = x[n] + sum_{nbr} x[s]
// Layer 1 (fp32 x) unchanged from R12; layer 2 reads packed-bf16 h1 (exact
// bf16->fp32 accumulate, half the gather traffic).
// ===========================================================================
__global__ void gather_split_64(const float* __restrict__ x) {
    int gw   = (blockIdx.x * blockDim.x + threadIdx.x) >> 5;
    int lane = threadIdx.x & 31;
    int nw   = (gridDim.x * blockDim.x) >> 5;
    for (int n = gw; n < NN; n += nw) {
        int lo = g_off[n], deg = g_cnt[n];
        float2 acc = __ldg((const float2*)(x + (size_t)n * 64) + lane);
        int i = 0;
        for (; i + 3 < deg; i += 4) {
            int s0 = __ldg(&g_ssrc[lo + i]);
            int s1 = __ldg(&g_ssrc[lo + i + 1]);
            int s2 = __ldg(&g_ssrc[lo + i + 2]);
            int s3 = __ldg(&g_ssrc[lo + i + 3]);
            float2 v0 = __ldg((const float2*)(x + (size_t)s0 * 64) + lane);
            float2 v1 = __ldg((const float2*)(x + (size_t)s1 * 64) + lane);
            float2 v2 = __ldg((const float2*)(x + (size_t)s2 * 64) + lane);
            float2 v3 = __ldg((const float2*)(x + (size_t)s3 * 64) + lane);
            acc.x += v0.x + v1.x + v2.x + v3.x;
            acc.y += v0.y + v1.y + v2.y + v3.y;
        }
        for (; i < deg; i++) {
            int s = __ldg(&g_ssrc[lo + i]);
            float2 v = __ldg((const float2*)(x + (size_t)s * 64) + lane);
            acc.x += v.x; acc.y += v.y;
        }
        uint32_t hp, lp;
        split2(acc.x, acc.y, hp, lp);
        g_aggHi[(size_t)n * 32 + lane] = hp;
        g_aggLo[(size_t)n * 32 + lane] = lp;
    }
}

// Layer 2: h1 is packed bf16x2 [NN][64]; lane handles channels [4*lane,4*lane+4)
__global__ void gather_split_128(const uint32_t* __restrict__ h1b) {
    int gw   = (blockIdx.x * blockDim.x + threadIdx.x) >> 5;
    int lane = threadIdx.x & 31;
    int nw   = (gridDim.x * blockDim.x) >> 5;
    for (int n = gw; n < NN; n += nw) {
        int lo = g_off[n], deg = g_cnt[n];
        uint2 a0 = __ldg((const uint2*)(h1b + (size_t)n * 64) + lane);
        float2 f0 = bf2f(a0.x), f1 = bf2f(a0.y);
        float4 acc = make_float4(f0.x, f0.y, f1.x, f1.y);
        int i = 0;
        for (; i + 3 < deg; i += 4) {
            int s0 = __ldg(&g_ssrc[lo + i]);
            int s1 = __ldg(&g_ssrc[lo + i + 1]);
            int s2 = __ldg(&g_ssrc[lo + i + 2]);
            int s3 = __ldg(&g_ssrc[lo + i + 3]);
            uint2 v0 = __ldg((const uint2*)(h1b + (size_t)s0 * 64) + lane);
            uint2 v1 = __ldg((const uint2*)(h1b + (size_t)s1 * 64) + lane);
            uint2 v2 = __ldg((const uint2*)(h1b + (size_t)s2 * 64) + lane);
            uint2 v3 = __ldg((const uint2*)(h1b + (size_t)s3 * 64) + lane);
            float2 a, b;
            a = bf2f(v0.x); b = bf2f(v0.y); acc.x += a.x; acc.y += a.y; acc.z += b.x; acc.w += b.y;
            a = bf2f(v1.x); b = bf2f(v1.y); acc.x += a.x; acc.y += a.y; acc.z += b.x; acc.w += b.y;
            a = bf2f(v2.x); b = bf2f(v2.y); acc.x += a.x; acc.y += a.y; acc.z += b.x; acc.w += b.y;
            a = bf2f(v3.x); b = bf2f(v3.y); acc.x += a.x; acc.y += a.y; acc.z += b.x; acc.w += b.y;
        }
        for (; i < deg; i++) {
            int s = __ldg(&g_ssrc[lo + i]);
            uint2 v = __ldg((const uint2*)(h1b + (size_t)s * 64) + lane);
            float2 a = bf2f(v.x), b = bf2f(v.y);
            acc.x += a.x; acc.y += a.y; acc.z += b.x; acc.w += b.y;
        }
        uint2 hp, lp;
        split2(acc.x, acc.y, hp.x, lp.x);
        split2(acc.z, acc.w, hp.y, lp.y);
        *(uint2*)(g_aggHi + (size_t)n * 64 + lane * 2) = hp;
        *(uint2*)(g_aggLo + (size_t)n * 64 + lane * 2) = lp;
    }
}

// ===========================================================================
// Fused GEMM pair with cp.async double-buffered A staging.
// POOL=false (layer 1): writes h1 as packed bf16x2 [NN][64].
// POOL=true  (layer 2): folds mean-pool + FC into the epilogue.
// ===========================================================================
template <int K, bool POOL>
__global__ __launch_bounds__(256, 1)
void fused_pair(const uint32_t* __restrict__ aggHi, const uint32_t* __restrict__ aggLo,
                const float* __restrict__ W1, const float* __restrict__ b1,
                const float* __restrict__ W2, const float* __restrict__ b2,
                uint32_t* __restrict__ outB,
                const int* __restrict__ batch, const float* __restrict__ Wfc,
                int ntiles)
{
    constexpr int KCH1 = K / 16;          // k-chunks of GEMM1
    constexpr int RSB1 = K * 2 + 16;      // sA row stride bytes (conflict-free, /16)
    constexpr int RSB2 = 128 * 2 + 16;    // sI row stride bytes
    constexpr int CH   = K * 2 / 16;      // 16B chunks per row per plane
    constexpr int ABUF = 128 * RSB1;      // one plane
    extern __shared__ __align__(16) char smem[];
    char* sIhi = smem + 4 * ABUF;
    char* sIlo = sIhi + 128 * RSB2;
    __shared__ float sRow[128];

    const int tid  = threadIdx.x;
    const int wid  = tid >> 5;
    const int lane = tid & 31;
    const uint32_t uIhi = smem_u32(sIhi), uIlo = smem_u32(sIlo);
    const uint32_t uA00 = smem_u32(smem);   // buf0 hi base; others by offset

    // ---- async stage of one tile's A planes into buffer b ----
    auto stage = [&](int tile, int b) {
        const int base = tile * 128;
        uint32_t sh = uA00 + (uint32_t)(2 * b) * ABUF;       // hi plane of buf b
        uint32_t sl = sh + ABUF;                              // lo plane
        for (int i = tid; i < 128 * CH; i += 256) {
            int row = i / CH;
            int j   = i - row * CH;
            int n   = base + row;
            bool v  = n < NN;
            int nc  = v ? n : 0;
            const char* gh = (const char*)(aggHi + (size_t)nc * (K / 2)) + j * 16;
            const char* gl = (const char*)(aggLo + (size_t)nc * (K / 2)) + j * 16;
            uint32_t so = (uint32_t)row * RSB1 + j * 16;
            cp_async16(sh + so, gh, v ? 16 : 0);
            cp_async16(sl + so, gl, v ? 16 : 0);
        }
    };

    // ---- Prologue: kick off tile-0 copy, overlapping with weight staging ----
    int tile0 = blockIdx.x;
    if (tile0 < ntiles) stage(tile0, 0);
    CP_COMMIT();

    // ---- Stage W1^T hi/lo into sI (temp), extract B1 fragments ----
    uint32_t B1hi[KCH1][2][2], B1lo[KCH1][2][2];
    for (int i = tid; i < K * 128; i += 256) {
        int k = i >> 7, n = i & 127;                  // W1[k][n], coalesced
        float w = __ldg(&W1[i]);
        __nv_bfloat16 hi = __float2bfloat16(w);
        __nv_bfloat16 lo = __float2bfloat16(w - __bfloat162float(hi));
        *(__nv_bfloat16*)(sIhi + n * RSB1 + k * 2) = hi;
        *(__nv_bfloat16*)(sIlo + n * RSB1 + k * 2) = lo;
    }
    __syncthreads();
    {
        int r = lane & 7, mat = (lane >> 3) & 1;
        #pragma unroll
        for (int j = 0; j < 2; j++) {
            int n = wid * 16 + j * 8 + r;
            #pragma unroll
            for (int c = 0; c < KCH1; c++) {
                uint32_t off = (uint32_t)n * RSB1 + c * 32 + mat * 16;
                ldmatrix_x2(B1hi[c][j], uIhi + off);
                ldmatrix_x2(B1lo[c][j], uIlo + off);
            }
        }
    }
    __syncthreads();

    // ---- Stage W2^T hi/lo into sI (temp), extract B2 fragments ----
    uint32_t B2hi[8][2][2], B2lo[8][2][2];
    for (int i = tid; i < 128 * 128; i += 256) {
        int k = i >> 7, n = i & 127;
        float w = __ldg(&W2[i]);
        __nv_bfloat16 hi = __float2bfloat16(w);
        __nv_bfloat16 lo = __float2bfloat16(w - __bfloat162float(hi));
        *(__nv_bfloat16*)(sIhi + n * RSB2 + k * 2) = hi;
        *(__nv_bfloat16*)(sIlo + n * RSB2 + k * 2) = lo;
    }
    if (tid < 128) sRow[tid] = 0.f;
    __syncthreads();
    {
        int r = lane & 7, mat = (lane >> 3) & 1;
        #pragma unroll
        for (int j = 0; j < 2; j++) {
            int n = wid * 16 + j * 8 + r;
            #pragma unroll
            for (int c = 0; c < 8; c++) {
                uint32_t off = (uint32_t)n * RSB2 + c * 32 + mat * 16;
                ldmatrix_x2(B2hi[c][j], uIhi + off);
                ldmatrix_x2(B2lo[c][j], uIlo + off);
            }
        }
    }
    __syncthreads();

    // Per-thread bias and Wfc scalars (cols fixed for the whole kernel)
    const int c0 = wid * 16 + (lane & 3) * 2;
    const float b1s00 = __ldg(&b1[c0]),     b1s01 = __ldg(&b1[c0 + 1]);
    const float b1s10 = __ldg(&b1[c0 + 8]), b1s11 = __ldg(&b1[c0 + 9]);
    const float b2s00 = __ldg(&b2[c0]),     b2s01 = __ldg(&b2[c0 + 1]);
    const float b2s10 = __ldg(&b2[c0 + 8]), b2s11 = __ldg(&b2[c0 + 9]);
    float wf00 = 0.f, wf01 = 0.f, wf10 = 0.f, wf11 = 0.f;
    if (POOL) {
        wf00 = __ldg(&Wfc[c0]);     wf01 = __ldg(&Wfc[c0 + 1]);
        wf10 = __ldg(&Wfc[c0 + 8]); wf11 = __ldg(&Wfc[c0 + 9]);
    }

    // ldmatrix.x4 lane address pattern for A (row-major 16x16)
    const int ar = (lane & 7) + ((lane & 8) ? 8 : 0);
    const int ak = (lane & 16) ? 16 : 0;

    int bsel = 0;
    for (int tile = tile0; tile < ntiles; tile += gridDim.x) {
        const int base = tile * 128;

        // ---- Prefetch next tile into the other buffer, then wait on current ----
        int nxt = tile + gridDim.x;
        if (nxt < ntiles) stage(nxt, bsel ^ 1);
        CP_COMMIT();
        CP_WAIT1();
        __syncthreads();

        const uint32_t uAhi = uA00 + (uint32_t)(2 * bsel) * ABUF;
        const uint32_t uAlo = uAhi + ABUF;

        // ---- GEMM1 (m-tile pairs) -> relu -> split -> sI ----
        #pragma unroll
        for (int mp = 0; mp < 4; mp++) {
            float acc[2][2][4];
            #pragma unroll
            for (int t = 0; t < 2; t++)
                #pragma unroll
                for (int j = 0; j < 2; j++)
                    #pragma unroll
                    for (int q = 0; q < 4; q++) acc[t][j][q] = 0.f;

            #pragma unroll
            for (int c = 0; c < KCH1; c++) {
                #pragma unroll
                for (int t = 0; t < 2; t++) {
                    uint32_t arow = (uint32_t)(mp * 32 + t * 16 + ar) * RSB1 + ak + c * 32;
                    uint32_t ahi[4], alo[4];
                    ldmatrix_x4(ahi, uAhi + arow);
                    ldmatrix_x4(alo, uAlo + arow);
                    #pragma unroll
                    for (int j = 0; j < 2; j++) {
                        mma_16816(acc[t][j], ahi, B1hi[c][j]);
                        mma_16816(acc[t][j], ahi, B1lo[c][j]);
                        mma_16816(acc[t][j], alo, B1hi[c][j]);
                    }
                }
            }
            #pragma unroll
            for (int t = 0; t < 2; t++) {
                int r0 = mp * 32 + t * 16 + (lane >> 2);
                int r1 = r0 + 8;
                #pragma unroll
                for (int j = 0; j < 2; j++) {
                    float bx = j ? b1s10 : b1s00;
                    float by = j ? b1s11 : b1s01;
                    int cc = wid * 16 + j * 8 + (lane & 3) * 2;
                    float v0 = fmaxf(acc[t][j][0] + bx, 0.f);
                    float v1 = fmaxf(acc[t][j][1] + by, 0.f);
                    float v2 = fmaxf(acc[t][j][2] + bx, 0.f);
                    float v3 = fmaxf(acc[t][j][3] + by, 0.f);
                    uint32_t hp, lp;
                    split2(v0, v1, hp, lp);
                    *(uint32_t*)(sIhi + r0 * RSB2 + cc * 2) = hp;
                    *(uint32_t*)(sIlo + r0 * RSB2 + cc * 2) = lp;
                    split2(v2, v3, hp, lp);
                    *(uint32_t*)(sIhi + r1 * RSB2 + cc * 2) = hp;
                    *(uint32_t*)(sIlo + r1 * RSB2 + cc * 2) = lp;
                }
            }
        }
        __syncthreads();

        // ---- GEMM2 (m-tile pairs) -> bias+relu -> bf16 h1 or pool ----
        #pragma unroll
        for (int mp = 0; mp < 4; mp++) {
            float acc[2][2][4];
            #pragma unroll
            for (int t = 0; t < 2; t++)
                #pragma unroll
                for (int j = 0; j < 2; j++)
                    #pragma unroll
                    for (int q = 0; q < 4; q++) acc[t][j][q] = 0.f;

            #pragma unroll
            for (int c = 0; c < 8; c++) {
                #pragma unroll
                for (int t = 0; t < 2; t++) {
                    uint32_t arow = (uint32_t)(mp * 32 + t * 16 + ar) * RSB2 + ak + c * 32;
                    uint32_t ahi[4], alo[4];
                    ldmatrix_x4(ahi, uIhi + arow);
                    ldmatrix_x4(alo, uIlo + arow);
                    #pragma unroll
                    for (int j = 0; j < 2; j++) {
                        mma_16816(acc[t][j], ahi, B2hi[c][j]);
                        mma_16816(acc[t][j], ahi, B2lo[c][j]);
                        mma_16816(acc[t][j], alo, B2hi[c][j]);
                    }
                }
            }
            #pragma unroll
            for (int t = 0; t < 2; t++) {
                int rl0 = mp * 32 + t * 16 + (lane >> 2);
                int rl1 = rl0 + 8;
                if (POOL) {
                    float p0 = 0.f, p1 = 0.f;
                    #pragma unroll
                    for (int j = 0; j < 2; j++) {
                        float bx = j ? b2s10 : b2s00;
                        float by = j ? b2s11 : b2s01;
                        float wx = j ? wf10 : wf00;
                        float wy = j ? wf11 : wf01;
                        p0 += fmaxf(acc[t][j][0] + bx, 0.f) * wx
                            + fmaxf(acc[t][j][1] + by, 0.f) * wy;
                        p1 += fmaxf(acc[t][j][2] + bx, 0.f) * wx
                            + fmaxf(acc[t][j][3] + by, 0.f) * wy;
                    }
                    p0 += __shfl_xor_sync(0xffffffffu, p0, 1);
                    p0 += __shfl_xor_sync(0xffffffffu, p0, 2);
                    p1 += __shfl_xor_sync(0xffffffffu, p1, 1);
                    p1 += __shfl_xor_sync(0xffffffffu, p1, 2);
                    if ((lane & 3) == 0) {
                        atomicAdd(&sRow[rl0], p0);
                        atomicAdd(&sRow[rl1], p1);
                    }
                } else {
                    int r0 = base + rl0;
                    int r1 = base + rl1;
                    #pragma unroll
                    for (int j = 0; j < 2; j++) {
                        float bx = j ? b2s10 : b2s00;
                        float by = j ? b2s11 : b2s01;
                        int cc = wid * 16 + j * 8 + (lane & 3) * 2;
                        if (r0 < NN)
                            outB[(size_t)r0 * 64 + (cc >> 1)] =
                                packbf(fmaxf(acc[t][j][0] + bx, 0.f),
                                       fmaxf(acc[t][j][1] + by, 0.f));
                        if (r1 < NN)
                            outB[(size_t)r1 * 64 + (cc >> 1)] =
                                packbf(fmaxf(acc[t][j][2] + bx, 0.f),
                                       fmaxf(acc[t][j][3] + by, 0.f));
                    }
                }
            }
        }
        if (POOL) {
            __syncthreads();
            for (int r = tid; r < 128; r += 256) {
                int n = base + r;
                if (n < NN) {
                    float v = sRow[r];
                    atomicAdd(&g_gsum[__ldg(&batch[n])], v);
                }
                sRow[r] = 0.f;
            }
        }
        __syncthreads();   // buf[bsel] reads + sI/sRow complete before reuse
        bsel ^= 1;
    }
}

// ===========================================================================
// counts per graph via binary search on the SORTED batch array
__global__ void finalize(const int* __restrict__ batch,
                         float* __restrict__ out, const float* __restrict__ bfc) {
    int g = threadIdx.x;
    if (g >= GG) return;
    int lo = 0, hi = NN;
    while (lo < hi) { int m = (lo + hi) >> 1; if (__ldg(&batch[m]) < g) lo = m + 1; else hi = m; }
    int lb = lo;
    lo = 0; hi = NN;
    while (lo < hi) { int m = (lo + hi) >> 1; if (__ldg(&batch[m]) < g + 1) lo = m + 1; else hi = m; }
    int cnt = lo - lb;
    out[g] = g_gsum[g] / fmaxf((float)cnt, 1.0f) + bfc[0];
}

// ===========================================================================
extern "C" void kernel_launch(void* const* d_in, const int* in_sizes, int n_in,
                              void* d_out, int out_size) {
    const float* x     = (const float*)d_in[0];
    const int*   ei    = (const int*)d_in[1];     // int32
    const int*   batch = (const int*)d_in[2];     // int32 (sorted)
    const float* W1a = (const float*)d_in[3];
    const float* b1a = (const float*)d_in[4];
    const float* W1b = (const float*)d_in[5];
    const float* b1b = (const float*)d_in[6];
    const float* W2a = (const float*)d_in[7];
    const float* b2a = (const float*)d_in[8];
    const float* W2b = (const float*)d_in[9];
    const float* b2b = (const float*)d_in[10];
    const float* Wfc = (const float*)d_in[11];
    const float* bfc = (const float*)d_in[12];
    float* out = (float*)d_out;

    const int* esrc = ei;
    const int* edst = ei + EE;

    uint32_t *h1b, *aggHi, *aggLo;
    cudaGetSymbolAddress((void**)&h1b, g_h1b);
    cudaGetSymbolAddress((void**)&aggHi, g_aggHi);
    cudaGetSymbolAddress((void**)&aggLo, g_aggLo);

    // smem: 4 A-planes (double-buffered hi/lo) + sI hi/lo
    const int smemF64  = 4 * 128 * (64 * 2 + 16) + 2 * 128 * (128 * 2 + 16);   // 143,360
    const int smemF128 = 4 * 128 * (128 * 2 + 16) + 2 * 128 * (128 * 2 + 16);  // 208,896
    cudaFuncSetAttribute(fused_pair<64, false>,  cudaFuncAttributeMaxDynamicSharedMemorySize, smemF64);
    cudaFuncSetAttribute(fused_pair<128, true>,  cudaFuncAttributeMaxDynamicSharedMemorySize, smemF128);

    const int ntiles = (NN + 127) / 128;   // 782

    // ---- CSR build (per call; reused by both layers) ----
    zero_cnt<<<(NN + 255) / 256, 256>>>();
    hist_kernel<<<(EE + 255) / 256, 256>>>(edst);
    scan_kernel<<<1, SCAN_T>>>();
    reorder_kernel<<<(EE + 255) / 256, 256>>>(esrc, edst);

    // ---- Layer 1 (writes h1 as packed bf16x2) ----
    gather_split_64<<<1024, 256>>>(x);
    fused_pair<64, false><<<148, 256, smemF64>>>(aggHi, aggLo, W1a, b1a, W1b, b1b,
                                                 h1b, nullptr, nullptr, ntiles);

    // ---- Layer 2 (bf16 gather; pool fused into epilogue) ----
    gather_split_128<<<1024, 256>>>(h1b);
    fused_pair<128, true><<<148, 256, smemF128>>>(aggHi, aggLo, W2a, b2a, W2b, b2b,
                                                  nullptr, batch, Wfc, ntiles);

    // ---- Finalize (counts via binary search on sorted batch) ----
    finalize<<<1, 256>>>(batch, out, bfc);
}

// round 16
// speedup vs baseline: 1.3511x; 1.1031x over previous
#include <cuda_runtime.h>
#include <cuda_bf16.h>
#include <cstdint>

constexpr int NN  = 100000;   // nodes
constexpr int EE  = 1600000;  // edges
constexpr int GG  = 256;      // graphs
constexpr int DIN = 64;
constexpr int HID = 128;

// Scratch (device globals — no allocation allowed)
__device__ uint32_t g_agg [(size_t)NN * 64];    // packed bf16x2 aggregate (K<=128)
__device__ uint32_t g_h1b [(size_t)NN * 64];    // h1 as packed bf16x2 [NN][64]
__device__ float g_gsum[GG];
// CSR scratch
__device__ int g_cnt [NN];
__device__ int g_off [NN];
__device__ int g_pos [EE];
__device__ int g_ssrc[EE];

// ===========================================================================
// Warp-level tensor-core + async-copy primitives (base ISA on target sm_100)
// ===========================================================================
__device__ __forceinline__ uint32_t smem_u32(const void* p) {
    uint32_t a;
    asm("{ .reg .u64 t; cvta.to.shared.u64 t, %1; cvt.u32.u64 %0, t; }" : "=r"(a) : "l"(p));
    return a;
}

__device__ __forceinline__ void ldmatrix_x4(uint32_t* r, uint32_t addr) {
    asm volatile("ldmatrix.sync.aligned.m8n8.x4.shared.b16 {%0,%1,%2,%3}, [%4];"
                 : "=r"(r[0]), "=r"(r[1]), "=r"(r[2]), "=r"(r[3]) : "r"(addr));
}
__device__ __forceinline__ void ldmatrix_x2(uint32_t* r, uint32_t addr) {
    asm volatile("ldmatrix.sync.aligned.m8n8.x2.shared.b16 {%0,%1}, [%2];"
                 : "=r"(r[0]), "=r"(r[1]) : "r"(addr));
}

// D(16x8,f32) += A(16x16,bf16,row) * B(16x8,bf16,col)
__device__ __forceinline__ void mma_16816(float* d, const uint32_t* a, const uint32_t* b) {
    asm volatile(
        "mma.sync.aligned.m16n8k16.row.col.f32.bf16.bf16.f32 "
        "{%0,%1,%2,%3}, {%4,%5,%6,%7}, {%8,%9}, {%0,%1,%2,%3};"
        : "+f"(d[0]), "+f"(d[1]), "+f"(d[2]), "+f"(d[3])
        : "r"(a[0]), "r"(a[1]), "r"(a[2]), "r"(a[3]), "r"(b[0]), "r"(b[1]));
}

// Split two floats into packed bf16x2 hi and lo words (weights only)
__device__ __forceinline__ void split2(float x, float y, uint32_t& hp, uint32_t& lp) {
    __nv_bfloat16 hx = __float2bfloat16(x), hy = __float2bfloat16(y);
    __nv_bfloat16 lx = __float2bfloat16(x - __bfloat162float(hx));
    __nv_bfloat16 ly = __float2bfloat16(y - __bfloat162float(hy));
    hp = ((uint32_t)__bfloat16_as_ushort(hy) << 16) | __bfloat16_as_ushort(hx);
    lp = ((uint32_t)__bfloat16_as_ushort(ly) << 16) | __bfloat16_as_ushort(lx);
}

__device__ __forceinline__ uint32_t packbf(float x, float y) {
    __nv_bfloat16 bx = __float2bfloat16(x), by = __float2bfloat16(y);
    return ((uint32_t)__bfloat16_as_ushort(by) << 16) | __bfloat16_as_ushort(bx);
}

// bf16x2 word -> two exact fp32 (bf16 bits << 16)
__device__ __forceinline__ float2 bf2f(uint32_t p) {
    float2 r;
    r.x = __uint_as_float(p << 16);
    r.y = __uint_as_float(p & 0xffff0000u);
    return r;
}

__device__ __forceinline__ void cp_async16(uint32_t saddr, const void* gaddr, int srcsz) {
    asm volatile("cp.async.cg.shared.global [%0], [%1], 16, %2;"
                 :: "r"(saddr), "l"(gaddr), "r"(srcsz) : "memory");
}
#define CP_COMMIT() asm volatile("cp.async.commit_group;" ::: "memory")
#define CP_WAIT1()  asm volatile("cp.async.wait_group 1;" ::: "memory")

// ===========================================================================
// CSR build: zero -> histogram(+slot) -> scan -> reorder
// ===========================================================================
__global__ void zero_cnt() {
    int t = blockIdx.x * blockDim.x + threadIdx.x;
    if (t < NN) g_cnt[t] = 0;
    if (t < GG) g_gsum[t] = 0.f;
}

__global__ void hist_kernel(const int* __restrict__ dst) {
    int e = blockIdx.x * blockDim.x + threadIdx.x;
    if (e < EE) g_pos[e] = atomicAdd(&g_cnt[__ldg(&dst[e])], 1);
}

constexpr int SCAN_T  = 1024;
constexpr int SCAN_CH = (NN + SCAN_T - 1) / SCAN_T;   // 98

__global__ void scan_kernel() {
    __shared__ int ssum[SCAN_T];
    int t = threadIdx.x;
    int base = t * SCAN_CH;
    int s = 0;
    #pragma unroll 4
    for (int i = 0; i < SCAN_CH; i++) {
        int j = base + i;
        if (j < NN) s += g_cnt[j];
    }
    ssum[t] = s;
    __syncthreads();
    for (int d = 1; d < SCAN_T; d <<= 1) {
        int v = (t >= d) ? ssum[t - d] : 0;
        __syncthreads();
        ssum[t] += v;
        __syncthreads();
    }
    int run = (t > 0) ? ssum[t - 1] : 0;
    for (int i = 0; i < SCAN_CH; i++) {
        int j = base + i;
        if (j < NN) { g_off[j] = run; run += g_cnt[j]; }
    }
}

__global__ void reorder_kernel(const int* __restrict__ src,
                               const int* __restrict__ dst) {
    int e = blockIdx.x * blockDim.x + threadIdx.x;
    if (e < EE) {
        int d = __ldg(&dst[e]);
        g_ssrc[g_off[d] + g_pos[e]] = __ldg(&src[e]);
    }
}

// ===========================================================================
// Gather aggregation -> single bf16 plane: agg[n] = x[n] + sum_{nbr} x[s]
// (fp32 accumulate; single bf16 rounding at the end — error independent per
//  node, washes out in mean-pool)
// ===========================================================================
__global__ void gather_split_64(const float* __restrict__ x) {
    int gw   = (blockIdx.x * blockDim.x + threadIdx.x) >> 5;
    int lane = threadIdx.x & 31;
    int nw   = (gridDim.x * blockDim.x) >> 5;
    for (int n = gw; n < NN; n += nw) {
        int lo = g_off[n], deg = g_cnt[n];
        float2 acc = __ldg((const float2*)(x + (size_t)n * 64) + lane);
        int i = 0;
        for (; i + 3 < deg; i += 4) {
            int s0 = __ldg(&g_ssrc[lo + i]);
            int s1 = __ldg(&g_ssrc[lo + i + 1]);
            int s2 = __ldg(&g_ssrc[lo + i + 2]);
            int s3 = __ldg(&g_ssrc[lo + i + 3]);
            float2 v0 = __ldg((const float2*)(x + (size_t)s0 * 64) + lane);
            float2 v1 = __ldg((const float2*)(x + (size_t)s1 * 64) + lane);
            float2 v2 = __ldg((const float2*)(x + (size_t)s2 * 64) + lane);
            float2 v3 = __ldg((const float2*)(x + (size_t)s3 * 64) + lane);
            acc.x += v0.x + v1.x + v2.x + v3.x;
            acc.y += v0.y + v1.y + v2.y + v3.y;
        }
        for (; i < deg; i++) {
            int s = __ldg(&g_ssrc[lo + i]);
            float2 v = __ldg((const float2*)(x + (size_t)s * 64) + lane);
            acc.x += v.x; acc.y += v.y;
        }
        g_agg[(size_t)n * 32 + lane] = packbf(acc.x, acc.y);
    }
}

// Layer 2: h1 is packed bf16x2 [NN][64]; lane handles channels [4*lane,4*lane+4)
__global__ void gather_split_128(const uint32_t* __restrict__ h1b) {
    int gw   = (blockIdx.x * blockDim.x + threadIdx.x) >> 5;
    int lane = threadIdx.x & 31;
    int nw   = (gridDim.x * blockDim.x) >> 5;
    for (int n = gw; n < NN; n += nw) {
        int lo = g_off[n], deg = g_cnt[n];
        uint2 a0 = __ldg((const uint2*)(h1b + (size_t)n * 64) + lane);
        float2 f0 = bf2f(a0.x), f1 = bf2f(a0.y);
        float4 acc = make_float4(f0.x, f0.y, f1.x, f1.y);
        int i = 0;
        for (; i + 3 < deg; i += 4) {
            int s0 = __ldg(&g_ssrc[lo + i]);
            int s1 = __ldg(&g_ssrc[lo + i + 1]);
            int s2 = __ldg(&g_ssrc[lo + i + 2]);
            int s3 = __ldg(&g_ssrc[lo + i + 3]);
            uint2 v0 = __ldg((const uint2*)(h1b + (size_t)s0 * 64) + lane);
            uint2 v1 = __ldg((const uint2*)(h1b + (size_t)s1 * 64) + lane);
            uint2 v2 = __ldg((const uint2*)(h1b + (size_t)s2 * 64) + lane);
            uint2 v3 = __ldg((const uint2*)(h1b + (size_t)s3 * 64) + lane);
            float2 a, b;
            a = bf2f(v0.x); b = bf2f(v0.y); acc.x += a.x; acc.y += a.y; acc.z += b.x; acc.w += b.y;
            a = bf2f(v1.x); b = bf2f(v1.y); acc.x += a.x; acc.y += a.y; acc.z += b.x; acc.w += b.y;
            a = bf2f(v2.x); b = bf2f(v2.y); acc.x += a.x; acc.y += a.y; acc.z += b.x; acc.w += b.y;
            a = bf2f(v3.x); b = bf2f(v3.y); acc.x += a.x; acc.y += a.y; acc.z += b.x; acc.w += b.y;
        }
        for (; i < deg; i++) {
            int s = __ldg(&g_ssrc[lo + i]);
            uint2 v = __ldg((const uint2*)(h1b + (size_t)s * 64) + lane);
            float2 a = bf2f(v.x), b = bf2f(v.y);
            acc.x += a.x; acc.y += a.y; acc.z += b.x; acc.w += b.y;
        }
        uint2 hp;
        hp.x = packbf(acc.x, acc.y);
        hp.y = packbf(acc.z, acc.w);
        *(uint2*)(g_agg + (size_t)n * 64 + lane * 2) = hp;
    }
}

// ===========================================================================
// Fused GEMM pair, 2-pass weight-split MMA (A single bf16 precision):
//   D = A_hi*(B_hi + B_lo)   — weight rounding corrected, A rounding pooled out
// cp.async double-buffered single-plane A staging.
// POOL=false (layer 1): writes h1 as packed bf16x2 [NN][64].
// POOL=true  (layer 2): folds mean-pool + FC into the epilogue.
// ===========================================================================
template <int K, bool POOL>
__global__ __launch_bounds__(256, 1)
void fused_pair(const uint32_t* __restrict__ agg,
                const float* __restrict__ W1, const float* __restrict__ b1,
                const float* __restrict__ W2, const float* __restrict__ b2,
                uint32_t* __restrict__ outB,
                const int* __restrict__ batch, const float* __restrict__ Wfc,
                int ntiles)
{
    constexpr int KCH1 = K / 16;          // k-chunks of GEMM1
    constexpr int RSB1 = K * 2 + 16;      // sA row stride bytes (conflict-free, /16)
    constexpr int RSB2 = 128 * 2 + 16;    // sI row stride bytes
    constexpr int CH   = K * 2 / 16;      // 16B chunks per row (single plane)
    constexpr int ABUF = 128 * RSB1;      // one A plane
    extern __shared__ __align__(16) char smem[];
    // layout: [A buf0][A buf1][sIhi][sIlo (weight-staging temp only)]
    char* sIhi = smem + 2 * ABUF;
    char* sIlo = sIhi + 128 * RSB2;
    __shared__ float sRow[128];

    const int tid  = threadIdx.x;
    const int wid  = tid >> 5;
    const int lane = tid & 31;
    const uint32_t uIhi = smem_u32(sIhi), uIlo = smem_u32(sIlo);
    const uint32_t uA0 = smem_u32(smem);

    // ---- async stage of one tile's A plane into buffer b ----
    auto stage = [&](int tile, int b) {
        const int base = tile * 128;
        uint32_t sh = uA0 + (uint32_t)b * ABUF;
        for (int i = tid; i < 128 * CH; i += 256) {
            int row = i / CH;
            int j   = i - row * CH;
            int n   = base + row;
            bool v  = n < NN;
            int nc  = v ? n : 0;
            const char* gh = (const char*)(agg + (size_t)nc * (K / 2)) + j * 16;
            cp_async16(sh + (uint32_t)row * RSB1 + j * 16, gh, v ? 16 : 0);
        }
    };

    // ---- Prologue: kick off tile-0 copy, overlapping with weight staging ----
    int tile0 = blockIdx.x;
    if (tile0 < ntiles) stage(tile0, 0);
    CP_COMMIT();

    // ---- Stage W1^T hi/lo into sI (temp), extract B1 fragments ----
    uint32_t B1hi[KCH1][2][2], B1lo[KCH1][2][2];
    for (int i = tid; i < K * 128; i += 256) {
        int k = i >> 7, n = i & 127;                  // W1[k][n], coalesced
        float w = __ldg(&W1[i]);
        __nv_bfloat16 hi = __float2bfloat16(w);
        __nv_bfloat16 lo = __float2bfloat16(w - __bfloat162float(hi));
        *(__nv_bfloat16*)(sIhi + n * RSB1 + k * 2) = hi;
        *(__nv_bfloat16*)(sIlo + n * RSB1 + k * 2) = lo;
    }
    __syncthreads();
    {
        int r = lane & 7, mat = (lane >> 3) & 1;
        #pragma unroll
        for (int j = 0; j < 2; j++) {
            int n = wid * 16 + j * 8 + r;
            #pragma unroll
            for (int c = 0; c < KCH1; c++) {
                uint32_t off = (uint32_t)n * RSB1 + c * 32 + mat * 16;
                ldmatrix_x2(B1hi[c][j], uIhi + off);
                ldmatrix_x2(B1lo[c][j], uIlo + off);
            }
        }
    }
    __syncthreads();

    // ---- Stage W2^T hi/lo into sI (temp), extract B2 fragments ----
    uint32_t B2hi[8][2][2], B2lo[8][2][2];
    for (int i = tid; i < 128 * 128; i += 256) {
        int k = i >> 7, n = i & 127;
        float w = __ldg(&W2[i]);
        __nv_bfloat16 hi = __float2bfloat16(w);
        __nv_bfloat16 lo = __float2bfloat16(w - __bfloat162float(hi));
        *(__nv_bfloat16*)(sIhi + n * RSB2 + k * 2) = hi;
        *(__nv_bfloat16*)(sIlo + n * RSB2 + k * 2) = lo;
    }
    if (tid < 128) sRow[tid] = 0.f;
    __syncthreads();
    {
        int r = lane & 7, mat = (lane >> 3) & 1;
        #pragma unroll
        for (int j = 0; j < 2; j++) {
            int n = wid * 16 + j * 8 + r;
            #pragma unroll
            for (int c = 0; c < 8; c++) {
                uint32_t off = (uint32_t)n * RSB2 + c * 32 + mat * 16;
                ldmatrix_x2(B2hi[c][j], uIhi + off);
                ldmatrix_x2(B2lo[c][j], uIlo + off);
            }
        }
    }
    __syncthreads();

    // Per-thread bias and Wfc scalars (cols fixed for the whole kernel)
    const int c0 = wid * 16 + (lane & 3) * 2;
    const float b1s00 = __ldg(&b1[c0]),     b1s01 = __ldg(&b1[c0 + 1]);
    const float b1s10 = __ldg(&b1[c0 + 8]), b1s11 = __ldg(&b1[c0 + 9]);
    const float b2s00 = __ldg(&b2[c0]),     b2s01 = __ldg(&b2[c0 + 1]);
    const float b2s10 = __ldg(&b2[c0 + 8]), b2s11 = __ldg(&b2[c0 + 9]);
    float wf00 = 0.f, wf01 = 0.f, wf10 = 0.f, wf11 = 0.f;
    if (POOL) {
        wf00 = __ldg(&Wfc[c0]);     wf01 = __ldg(&Wfc[c0 + 1]);
        wf10 = __ldg(&Wfc[c0 + 8]); wf11 = __ldg(&Wfc[c0 + 9]);
    }

    // ldmatrix.x4 lane address pattern for A (row-major 16x16)
    const int ar = (lane & 7) + ((lane & 8) ? 8 : 0);
    const int ak = (lane & 16) ? 16 : 0;

    int bsel = 0;
    for (int tile = tile0; tile < ntiles; tile += gridDim.x) {
        const int base = tile * 128;

        // ---- Prefetch next tile into the other buffer, then wait on current ----
        int nxt = tile + gridDim.x;
        if (nxt < ntiles) stage(nxt, bsel ^ 1);
        CP_COMMIT();
        CP_WAIT1();
        __syncthreads();

        const uint32_t uAhi = uA0 + (uint32_t)bsel * ABUF;

        // ---- GEMM1 (m-tile pairs, 2-pass) -> relu -> bf16 -> sIhi ----
        #pragma unroll
        for (int mp = 0; mp < 4; mp++) {
            float acc[2][2][4];
            #pragma unroll
            for (int t = 0; t < 2; t++)
                #pragma unroll
                for (int j = 0; j < 2; j++)
                    #pragma unroll
                    for (int q = 0; q < 4; q++) acc[t][j][q] = 0.f;

            #pragma unroll
            for (int c = 0; c < KCH1; c++) {
                #pragma unroll
                for (int t = 0; t < 2; t++) {
                    uint32_t arow = (uint32_t)(mp * 32 + t * 16 + ar) * RSB1 + ak + c * 32;
                    uint32_t ahi[4];
                    ldmatrix_x4(ahi, uAhi + arow);
                    #pragma unroll
                    for (int j = 0; j < 2; j++) {
                        mma_16816(acc[t][j], ahi, B1hi[c][j]);
                        mma_16816(acc[t][j], ahi, B1lo[c][j]);
                    }
                }
            }
            #pragma unroll
            for (int t = 0; t < 2; t++) {
                int r0 = mp * 32 + t * 16 + (lane >> 2);
                int r1 = r0 + 8;
                #pragma unroll
                for (int j = 0; j < 2; j++) {
                    float bx = j ? b1s10 : b1s00;
                    float by = j ? b1s11 : b1s01;
                    int cc = wid * 16 + j * 8 + (lane & 3) * 2;
                    *(uint32_t*)(sIhi + r0 * RSB2 + cc * 2) =
                        packbf(fmaxf(acc[t][j][0] + bx, 0.f),
                               fmaxf(acc[t][j][1] + by, 0.f));
                    *(uint32_t*)(sIhi + r1 * RSB2 + cc * 2) =
                        packbf(fmaxf(acc[t][j][2] + bx, 0.f),
                               fmaxf(acc[t][j][3] + by, 0.f));
                }
            }
        }
        __syncthreads();

        // ---- GEMM2 (m-tile pairs, 2-pass) -> bias+relu -> bf16 h1 or pool ----
        #pragma unroll
        for (int mp = 0; mp < 4; mp++) {
            float acc[2][2][4];
            #pragma unroll
            for (int t = 0; t < 2; t++)
                #pragma unroll
                for (int j = 0; j < 2; j++)
                    #pragma unroll
                    for (int q = 0; q < 4; q++) acc[t][j][q] = 0.f;

            #pragma unroll
            for (int c = 0; c < 8; c++) {
                #pragma unroll
                for (int t = 0; t < 2; t++) {
                    uint32_t arow = (uint32_t)(mp * 32 + t * 16 + ar) * RSB2 + ak + c * 32;
                    uint32_t ahi[4];
                    ldmatrix_x4(ahi, uIhi + arow);
                    #pragma unroll
                    for (int j = 0; j < 2; j++) {
                        mma_16816(acc[t][j], ahi, B2hi[c][j]);
                        mma_16816(acc[t][j], ahi, B2lo[c][j]);
                    }
                }
            }
            #pragma unroll
            for (int t = 0; t < 2; t++) {
                int rl0 = mp * 32 + t * 16 + (lane >> 2);
                int rl1 = rl0 + 8;
                if (POOL) {
                    float p0 = 0.f, p1 = 0.f;
                    #pragma unroll
                    for (int j = 0; j < 2; j++) {
                        float bx = j ? b2s10 : b2s00;
                        float by = j ? b2s11 : b2s01;
                        float wx = j ? wf10 : wf00;
                        float wy = j ? wf11 : wf01;
                        p0 += fmaxf(acc[t][j][0] + bx, 0.f) * wx
                            + fmaxf(acc[t][j][1] + by, 0.f) * wy;
                        p1 += fmaxf(acc[t][j][2] + bx, 0.f) * wx
                            + fmaxf(acc[t][j][3] + by, 0.f) * wy;
                    }
                    p0 += __shfl_xor_sync(0xffffffffu, p0, 1);
                    p0 += __shfl_xor_sync(0xffffffffu, p0, 2);
                    p1 += __shfl_xor_sync(0xffffffffu, p1, 1);
                    p1 += __shfl_xor_sync(0xffffffffu, p1, 2);
                    if ((lane & 3) == 0) {
                        atomicAdd(&sRow[rl0], p0);
                        atomicAdd(&sRow[rl1], p1);
                    }
                } else {
                    int r0 = base + rl0;
                    int r1 = base + rl1;
                    #pragma unroll
                    for (int j = 0; j < 2; j++) {
                        float bx = j ? b2s10 : b2s00;
                        float by = j ? b2s11 : b2s01;
                        int cc = wid * 16 + j * 8 + (lane & 3) * 2;
                        if (r0 < NN)
                            outB[(size_t)r0 * 64 + (cc >> 1)] =
                                packbf(fmaxf(acc[t][j][0] + bx, 0.f),
                                       fmaxf(acc[t][j][1] + by, 0.f));
                        if (r1 < NN)
                            outB[(size_t)r1 * 64 + (cc >> 1)] =
                                packbf(fmaxf(acc[t][j][2] + bx, 0.f),
                                       fmaxf(acc[t][j][3] + by, 0.f));
                    }
                }
            }
        }
        if (POOL) {
            __syncthreads();
            for (int r = tid; r < 128; r += 256) {
                int n = base + r;
                if (n < NN) {
                    float v = sRow[r];
                    atomicAdd(&g_gsum[__ldg(&batch[n])], v);
                }
                sRow[r] = 0.f;
            }
        }
        __syncthreads();   // buf[bsel] reads + sI/sRow complete before reuse
        bsel ^= 1;
    }
}

// ===========================================================================
// counts per graph via binary search on the SORTED batch array
__global__ void finalize(const int* __restrict__ batch,
                         float* __restrict__ out, const float* __restrict__ bfc) {
    int g = threadIdx.x;
    if (g >= GG) return;
    int lo = 0, hi = NN;
    while (lo < hi) { int m = (lo + hi) >> 1; if (__ldg(&batch[m]) < g) lo = m + 1; else hi = m; }
    int lb = lo;
    lo = 0; hi = NN;
    while (lo < hi) { int m = (lo + hi) >> 1; if (__ldg(&batch[m]) < g + 1) lo = m + 1; else hi = m; }
    int cnt = lo - lb;
    out[g] = g_gsum[g] / fmaxf((float)cnt, 1.0f) + bfc[0];
}

// ===========================================================================
extern "C" void kernel_launch(void* const* d_in, const int* in_sizes, int n_in,
                              void* d_out, int out_size) {
    const float* x     = (const float*)d_in[0];
    const int*   ei    = (const int*)d_in[1];     // int32
    const int*   batch = (const int*)d_in[2];     // int32 (sorted)
    const float* W1a = (const float*)d_in[3];
    const float* b1a = (const float*)d_in[4];
    const float* W1b = (const float*)d_in[5];
    const float* b1b = (const float*)d_in[6];
    const float* W2a = (const float*)d_in[7];
    const float* b2a = (const float*)d_in[8];
    const float* W2b = (const float*)d_in[9];
    const float* b2b = (const float*)d_in[10];
    const float* Wfc = (const float*)d_in[11];
    const float* bfc = (const float*)d_in[12];
    float* out = (float*)d_out;

    const int* esrc = ei;
    const int* edst = ei + EE;

    uint32_t *h1b, *agg;
    cudaGetSymbolAddress((void**)&h1b, g_h1b);
    cudaGetSymbolAddress((void**)&agg, g_agg);

    // smem: 2 single-plane A buffers + sI hi/lo (lo = weight temp only)
    const int smemF64  = 2 * 128 * (64 * 2 + 16) + 2 * 128 * (128 * 2 + 16);   // 106,496
    const int smemF128 = 2 * 128 * (128 * 2 + 16) + 2 * 128 * (128 * 2 + 16);  // 139,264
    cudaFuncSetAttribute(fused_pair<64, false>,  cudaFuncAttributeMaxDynamicSharedMemorySize, smemF64);
    cudaFuncSetAttribute(fused_pair<128, true>,  cudaFuncAttributeMaxDynamicSharedMemorySize, smemF128);

    const int ntiles = (NN + 127) / 128;   // 782

    // ---- CSR build (per call; reused by both layers) ----
    zero_cnt<<<(NN + 255) / 256, 256>>>();
    hist_kernel<<<(EE + 255) / 256, 256>>>(edst);
    scan_kernel<<<1, SCAN_T>>>();
    reorder_kernel<<<(EE + 255) / 256, 256>>>(esrc, edst);

    // ---- Layer 1 (writes h1 as packed bf16x2) ----
    gather_split_64<<<1024, 256>>>(x);
    fused_pair<64, false><<<148, 256, smemF64>>>(agg, W1a, b1a, W1b, b1b,
                                                 h1b, nullptr, nullptr, ntiles);

    // ---- Layer 2 (bf16 gather; pool fused into epilogue) ----
    gather_split_128<<<1024, 256>>>(h1b);
    fused_pair<128, true><<<148, 256, smemF128>>>(agg, W2a, b2a, W2b, b2b,
                                                  nullptr, batch, Wfc, ntiles);

    // ---- Finalize (counts via binary search on sorted batch) ----
    finalize<<<1, 256>>>(batch, out, bfc);
}